// round 1
// baseline (speedup 1.0000x reference)
#include <cuda_runtime.h>
#include <math.h>

#define NPTS 100000
#define CDIM 1024
#define DDIM 256

// Scratch (no allocations allowed): Phi [C, D] and p2 [C]
__device__ float g_Phi[CDIM * DDIM];
__device__ float g_p2[CDIM];

// ---------------------------------------------------------------------------
// Kernel 1: Phi = matrix_parents (1024x1024) @ epsilon (1024x256)
// 64x64 tile, BK=16, 256 threads, 4x4 per thread.
// ---------------------------------------------------------------------------
__global__ __launch_bounds__(256) void phi_kernel(const float* __restrict__ A,
                                                  const float* __restrict__ B) {
    __shared__ __align__(16) float As[16][64];
    __shared__ __align__(16) float Bs[16][64];
    const int tid = threadIdx.x;
    const int tx = tid & 15, ty = tid >> 4;
    const int m0 = blockIdx.y * 64;
    const int n0 = blockIdx.x * 64;
    float acc[4][4] = {};

    for (int k0 = 0; k0 < CDIM; k0 += 16) {
        __syncthreads();
        {   // A tile 64x16, store transposed As[k][m]
            int row = tid >> 2, c4 = tid & 3;
            float4 v = *reinterpret_cast<const float4*>(&A[(m0 + row) * CDIM + k0 + c4 * 4]);
            As[c4 * 4 + 0][row] = v.x;
            As[c4 * 4 + 1][row] = v.y;
            As[c4 * 4 + 2][row] = v.z;
            As[c4 * 4 + 3][row] = v.w;
        }
        {   // B tile 16x64
            int row = tid >> 4, c4 = tid & 15;
            *reinterpret_cast<float4*>(&Bs[row][c4 * 4]) =
                *reinterpret_cast<const float4*>(&B[(k0 + row) * DDIM + n0 + c4 * 4]);
        }
        __syncthreads();
#pragma unroll
        for (int k = 0; k < 16; ++k) {
            float4 ra = *reinterpret_cast<const float4*>(&As[k][ty * 4]);
            float4 rb = *reinterpret_cast<const float4*>(&Bs[k][tx * 4]);
            float a[4] = {ra.x, ra.y, ra.z, ra.w};
            float b[4] = {rb.x, rb.y, rb.z, rb.w};
#pragma unroll
            for (int i = 0; i < 4; ++i)
#pragma unroll
                for (int j = 0; j < 4; ++j)
                    acc[i][j] = fmaf(a[i], b[j], acc[i][j]);
        }
    }
#pragma unroll
    for (int i = 0; i < 4; ++i) {
        float4 v = make_float4(acc[i][0], acc[i][1], acc[i][2], acc[i][3]);
        *reinterpret_cast<float4*>(&g_Phi[(m0 + ty * 4 + i) * DDIM + n0 + tx * 4]) = v;
    }
}

// ---------------------------------------------------------------------------
// Kernel 2: p2[c] = sum_d Phi[c][d]^2   (one warp per row)
// ---------------------------------------------------------------------------
__global__ __launch_bounds__(256) void p2_kernel() {
    int w = (blockIdx.x * blockDim.x + threadIdx.x) >> 5;
    int lane = threadIdx.x & 31;
    if (w >= CDIM) return;
    const float4* r = reinterpret_cast<const float4*>(&g_Phi[w * DDIM]);
    float4 a = r[lane];
    float4 b = r[lane + 32];
    float s = a.x * a.x + a.y * a.y + a.z * a.z + a.w * a.w
            + b.x * b.x + b.y * b.y + b.z * b.z + b.w * b.w;
#pragma unroll
    for (int o = 16; o > 0; o >>= 1)
        s += __shfl_xor_sync(0xFFFFFFFFu, s, o);
    if (lane == 0) g_p2[w] = s;
}

// ---------------------------------------------------------------------------
// Kernel 3: fused dots + argmin + min_dist
// Block: 128 rows of X, loops over 8 column tiles of 128 centroids.
// 256 threads (16x16), 8x8 accumulators split as 4+4 (rows: ty*4 / 64+ty*4,
// cols: tx*4 / 64+tx*4) for conflict-free float4 shared loads.
// score = p2[c] - 2*dot; running (bestv, besti) in regs; final 16-wide
// reduction + on-the-fly ||x||^2 + sqrt.
// ---------------------------------------------------------------------------
__global__ __launch_bounds__(256) void dist_kernel(const float* __restrict__ X,
                                                   float* __restrict__ out) {
    __shared__ __align__(16) float Xs[16][128];
    __shared__ __align__(16) float Ps[16][128];
    __shared__ float red_v[128][16];
    __shared__ int   red_i[128][16];

    const int tid = threadIdx.x;
    const int tx = tid & 15, ty = tid >> 4;
    const int rowBase = blockIdx.x * 128;

    float bestv[8];
    int   besti[8];
#pragma unroll
    for (int i = 0; i < 8; ++i) { bestv[i] = 3.402823466e38f; besti[i] = 0; }

    for (int ct = 0; ct < CDIM / 128; ++ct) {
        const int colBase = ct * 128;
        float acc[8][8] = {};
        for (int k0 = 0; k0 < DDIM; k0 += 16) {
            __syncthreads();
#pragma unroll
            for (int t = 0; t < 2; ++t) {       // X tile 128x16 -> Xs[k][m]
                int f = tid + t * 256;
                int row = f >> 2, c4 = f & 3;
                int gr = rowBase + row;
                float4 v = make_float4(0.f, 0.f, 0.f, 0.f);
                if (gr < NPTS)
                    v = *reinterpret_cast<const float4*>(&X[(size_t)gr * DDIM + k0 + c4 * 4]);
                Xs[c4 * 4 + 0][row] = v.x;
                Xs[c4 * 4 + 1][row] = v.y;
                Xs[c4 * 4 + 2][row] = v.z;
                Xs[c4 * 4 + 3][row] = v.w;
            }
#pragma unroll
            for (int t = 0; t < 2; ++t) {       // Phi tile 128x16 -> Ps[k][n]
                int f = tid + t * 256;
                int row = f >> 2, c4 = f & 3;
                int gc = colBase + row;
                float4 v = *reinterpret_cast<const float4*>(&g_Phi[gc * DDIM + k0 + c4 * 4]);
                Ps[c4 * 4 + 0][row] = v.x;
                Ps[c4 * 4 + 1][row] = v.y;
                Ps[c4 * 4 + 2][row] = v.z;
                Ps[c4 * 4 + 3][row] = v.w;
            }
            __syncthreads();
#pragma unroll
            for (int k = 0; k < 16; ++k) {
                float4 x0 = *reinterpret_cast<const float4*>(&Xs[k][ty * 4]);
                float4 x1 = *reinterpret_cast<const float4*>(&Xs[k][64 + ty * 4]);
                float4 p0 = *reinterpret_cast<const float4*>(&Ps[k][tx * 4]);
                float4 p1 = *reinterpret_cast<const float4*>(&Ps[k][64 + tx * 4]);
                float rx[8] = {x0.x, x0.y, x0.z, x0.w, x1.x, x1.y, x1.z, x1.w};
                float rp[8] = {p0.x, p0.y, p0.z, p0.w, p1.x, p1.y, p1.z, p1.w};
#pragma unroll
                for (int i = 0; i < 8; ++i)
#pragma unroll
                    for (int j = 0; j < 8; ++j)
                        acc[i][j] = fmaf(rx[i], rp[j], acc[i][j]);
            }
        }
        // Fold this column tile into the running argmin (registers only).
#pragma unroll
        for (int j = 0; j < 8; ++j) {
            int cl = (j < 4) ? (tx * 4 + j) : (64 + tx * 4 + (j - 4));
            int c = colBase + cl;
            float p2c = g_p2[c];
#pragma unroll
            for (int i = 0; i < 8; ++i) {
                float s = fmaf(-2.f, acc[i][j], p2c);
                if (s < bestv[i]) { bestv[i] = s; besti[i] = c; }
            }
        }
    }

    // Cross-thread reduction: 16 candidates per row.
#pragma unroll
    for (int i = 0; i < 8; ++i) {
        int r = (i < 4) ? (ty * 4 + i) : (64 + ty * 4 + (i - 4));
        red_v[r][tx] = bestv[i];
        red_i[r][tx] = besti[i];
    }
    __syncthreads();

    if (tid < 128) {
        int gr = rowBase + tid;
        if (gr < NPTS) {
            float bv = red_v[tid][0];
            int   bi = red_i[tid][0];
#pragma unroll
            for (int t = 1; t < 16; ++t) {
                float v = red_v[tid][t];
                int   ii = red_i[tid][t];
                if (v < bv || (v == bv && ii < bi)) { bv = v; bi = ii; }
            }
            // ||x||^2 on the fly (row is L2-hot from the GEMM)
            const float4* xr = reinterpret_cast<const float4*>(&X[(size_t)gr * DDIM]);
            float x2 = 0.f;
#pragma unroll 8
            for (int t = 0; t < 64; ++t) {
                float4 v = xr[t];
                x2 += v.x * v.x + v.y * v.y + v.z * v.z + v.w * v.w;
            }
            float d2 = fmaxf(x2 + bv, 0.f);
            out[gr]        = (float)bi;      // pred (argmin index)
            out[NPTS + gr] = sqrtf(d2);      // min distance
        }
    }
}

// ---------------------------------------------------------------------------
extern "C" void kernel_launch(void* const* d_in, const int* in_sizes, int n_in,
                              void* d_out, int out_size) {
    const float* X = (const float*)d_in[0];              // [N, D]
    const float* parents = (const float*)d_in[1];        // [C, C]
    const float* epsilon = (const float*)d_in[2];        // [C, D]
    float* out = (float*)d_out;                          // [2*N] = pred | min_dist

    phi_kernel<<<dim3(DDIM / 64, CDIM / 64), 256>>>(parents, epsilon);
    p2_kernel<<<(CDIM * 32) / 256, 256>>>();
    dist_kernel<<<(NPTS + 127) / 128, 256>>>(X, out);
}

// round 5
// speedup vs baseline: 1.9534x; 1.9534x over previous
#include <cuda_runtime.h>
#include <cuda_bf16.h>
#include <math.h>

#define NPTS 100000
#define CDIM 1024
#define DDIM 256
#define THRESH 1.0f

// Scratch (no allocations allowed)
__device__ __align__(16) float g_Phi[CDIM * DDIM];
__device__ __align__(16) __nv_bfloat16 g_PhiH[CDIM * DDIM];
__device__ __align__(16) __nv_bfloat16 g_PhiL[CDIM * DDIM];
__device__ float g_p2[CDIM];
__device__ int g_cnt;
__device__ int g_list[NPTS];

// ---------------------------------------------------------------------------
// PTX helpers
// ---------------------------------------------------------------------------
static __device__ __forceinline__ unsigned smem_u32(const void* p) {
    return (unsigned)__cvta_generic_to_shared(p);
}

#define LDSM4(r0, r1, r2, r3, addr)                                            \
    asm volatile("ldmatrix.sync.aligned.m8n8.x4.shared.b16 {%0,%1,%2,%3}, [%4];" \
                 : "=r"(r0), "=r"(r1), "=r"(r2), "=r"(r3) : "r"(addr))

#define MMA16816(c, a, b)                                                      \
    asm volatile("mma.sync.aligned.m16n8k16.row.col.f32.bf16.bf16.f32 "        \
                 "{%0,%1,%2,%3}, {%4,%5,%6,%7}, {%8,%9}, {%0,%1,%2,%3};"       \
                 : "+f"((c)[0]), "+f"((c)[1]), "+f"((c)[2]), "+f"((c)[3])      \
                 : "r"((a)[0]), "r"((a)[1]), "r"((a)[2]), "r"((a)[3]),         \
                   "r"((b)[0]), "r"((b)[1]))

#define CP_ASYNC16(dst, src)                                                   \
    asm volatile("cp.async.cg.shared.global [%0], [%1], 16;" :: "r"(dst), "l"(src))
#define CP_COMMIT() asm volatile("cp.async.commit_group;")
#define CP_WAIT1()  asm volatile("cp.async.wait_group 1;")
#define CP_WAIT0()  asm volatile("cp.async.wait_group 0;")

static __device__ __forceinline__ void split_bf16(float v, __nv_bfloat16& h,
                                                  __nv_bfloat16& l) {
    h = __float2bfloat16_rn(v);
    l = __float2bfloat16_rn(v - __bfloat162float(h));
}

// ---------------------------------------------------------------------------
// Kernel 1: Phi = parents @ epsilon. Per-element k ascends 0..1023 in a single
// fp32 fmaf chain (same as the R1 kernel that matched the reference bitwise).
// 64x32 tiles -> 128 blocks for better chip fill.
// ---------------------------------------------------------------------------
__global__ __launch_bounds__(256) void phi_kernel(const float* __restrict__ A,
                                                  const float* __restrict__ B) {
    __shared__ __align__(16) float As[16][64];
    __shared__ __align__(16) float Bs[16][36];
    const int tid = threadIdx.x;
    const int tx = tid & 15, ty = tid >> 4;
    const int m0 = blockIdx.y * 64;
    const int n0 = blockIdx.x * 32;
    float acc[4][2] = {};

    for (int k0 = 0; k0 < CDIM; k0 += 16) {
        __syncthreads();
        {   // A tile 64x16 -> As[k][m] (transposed)
            int row = tid >> 2, c4 = tid & 3;
            float4 v = *reinterpret_cast<const float4*>(&A[(m0 + row) * CDIM + k0 + c4 * 4]);
            As[c4 * 4 + 0][row] = v.x;
            As[c4 * 4 + 1][row] = v.y;
            As[c4 * 4 + 2][row] = v.z;
            As[c4 * 4 + 3][row] = v.w;
        }
        if (tid < 128) {   // B tile 16x32
            int row = tid >> 3, c8 = tid & 7;
            float4 v = *reinterpret_cast<const float4*>(&B[(k0 + row) * DDIM + n0 + c8 * 4]);
            Bs[row][c8 * 4 + 0] = v.x;
            Bs[row][c8 * 4 + 1] = v.y;
            Bs[row][c8 * 4 + 2] = v.z;
            Bs[row][c8 * 4 + 3] = v.w;
        }
        __syncthreads();
#pragma unroll
        for (int k = 0; k < 16; ++k) {
            float4 ra = *reinterpret_cast<const float4*>(&As[k][ty * 4]);
            float a[4] = {ra.x, ra.y, ra.z, ra.w};
            float b0 = Bs[k][tx * 2];
            float b1 = Bs[k][tx * 2 + 1];
#pragma unroll
            for (int i = 0; i < 4; ++i) {
                acc[i][0] = fmaf(a[i], b0, acc[i][0]);
                acc[i][1] = fmaf(a[i], b1, acc[i][1]);
            }
        }
    }
#pragma unroll
    for (int i = 0; i < 4; ++i) {
        float2 v = make_float2(acc[i][0], acc[i][1]);
        *reinterpret_cast<float2*>(&g_Phi[(m0 + ty * 4 + i) * DDIM + n0 + tx * 2]) = v;
    }
}

// ---------------------------------------------------------------------------
// Kernel 2: p2[c] = ||Phi_c||^2 (fp32) + hi/lo bf16 split of Phi.
// ---------------------------------------------------------------------------
__global__ __launch_bounds__(256) void p2_kernel() {
    int w = (blockIdx.x * blockDim.x + threadIdx.x) >> 5;
    int lane = threadIdx.x & 31;
    if (w >= CDIM) return;
    const float4* r = reinterpret_cast<const float4*>(&g_Phi[w * DDIM]);
    float4 a = r[lane];
    float4 b = r[lane + 32];
    __nv_bfloat16* dh = &g_PhiH[w * DDIM];
    __nv_bfloat16* dl = &g_PhiL[w * DDIM];
    float va[8] = {a.x, a.y, a.z, a.w, b.x, b.y, b.z, b.w};
    __nv_bfloat16 hh[8], ll[8];
#pragma unroll
    for (int i = 0; i < 8; ++i) split_bf16(va[i], hh[i], ll[i]);
#pragma unroll
    for (int i = 0; i < 4; ++i) {
        dh[lane * 4 + i]       = hh[i];
        dl[lane * 4 + i]       = ll[i];
        dh[128 + lane * 4 + i] = hh[4 + i];
        dl[128 + lane * 4 + i] = ll[4 + i];
    }
    float s = a.x * a.x + a.y * a.y + a.z * a.z + a.w * a.w
            + b.x * b.x + b.y * b.y + b.z * b.z + b.w * b.w;
#pragma unroll
    for (int o = 16; o > 0; o >>= 1)
        s += __shfl_xor_sync(0xFFFFFFFFu, s, o);
    if (lane == 0) g_p2[w] = s;
}

// ---------------------------------------------------------------------------
// Kernel 3: split-bf16 tensor-core dots + argmin with second-best margin.
// Rows with margin < THRESH are pushed to g_list for exact fp32 refinement.
// ---------------------------------------------------------------------------
#define XS_STRIDE 264                  // bf16 elems per row (256 + 8 pad)
#define PS_STRIDE 40                   // bf16 elems per row (32 + 8 pad)
#define XS_BYTES  (128 * XS_STRIDE * 2)      // 67584
#define PS_BYTES  (128 * PS_STRIDE * 2)      // 10240 per buffer
#define SMEM_TOTAL (2 * XS_BYTES + 4 * PS_BYTES)  // 176128

__global__ __launch_bounds__(256, 1) void dist_kernel(const float* __restrict__ X,
                                                      float* __restrict__ out) {
    extern __shared__ __align__(16) char smem[];
    __nv_bfloat16* Xh = reinterpret_cast<__nv_bfloat16*>(smem);
    __nv_bfloat16* Xl = reinterpret_cast<__nv_bfloat16*>(smem + XS_BYTES);
    char* PsBase = smem + 2 * XS_BYTES;   // 4 buffers: H0 H1 L0 L1
    // Reduction arrays alias the Ps buffers (used only after mainloop).
    float* red_v = reinterpret_cast<float*>(PsBase);
    int*   red_i = reinterpret_cast<int*>(PsBase + 128 * 16 * 4);
    float* red_s = reinterpret_cast<float*>(PsBase + 2 * 128 * 16 * 4);

    const int tid = threadIdx.x;
    const int lane = tid & 31, wid = tid >> 5;
    const int wm = wid >> 2, wn = wid & 3;
    const int mBase = wm * 64, nBase = wn * 32;
    const int rowBase = blockIdx.x * 128;

    // ---- Load X tile (fp32 -> hi/lo bf16) ----
    for (int i = tid; i < 128 * 64; i += 256) {
        int r = i >> 6, q = i & 63;
        int gr = rowBase + r;
        float4 v = make_float4(0.f, 0.f, 0.f, 0.f);
        if (gr < NPTS)
            v = *reinterpret_cast<const float4*>(&X[(size_t)gr * DDIM + q * 4]);
        float va[4] = {v.x, v.y, v.z, v.w};
        __nv_bfloat16 hh[4], ll[4];
#pragma unroll
        for (int t = 0; t < 4; ++t) split_bf16(va[t], hh[t], ll[t]);
        *reinterpret_cast<__nv_bfloat162*>(&Xh[r * XS_STRIDE + q * 4]) =
            __nv_bfloat162(hh[0], hh[1]);
        *reinterpret_cast<__nv_bfloat162*>(&Xh[r * XS_STRIDE + q * 4 + 2]) =
            __nv_bfloat162(hh[2], hh[3]);
        *reinterpret_cast<__nv_bfloat162*>(&Xl[r * XS_STRIDE + q * 4]) =
            __nv_bfloat162(ll[0], ll[1]);
        *reinterpret_cast<__nv_bfloat162*>(&Xl[r * XS_STRIDE + q * 4 + 2]) =
            __nv_bfloat162(ll[2], ll[3]);
    }
    __syncthreads();

    // ldmatrix lane addressing
    const int arow = lane & 15;
    const int ahalf = lane >> 4;
    const int brow = (lane & 7) | ((lane >> 1) & 8);
    const int bhalf = (lane >> 3) & 1;

    const unsigned XhB = smem_u32(Xh);
    const unsigned XlB = smem_u32(Xl);
    const unsigned PsB = smem_u32(PsBase);
    const unsigned aOff = (unsigned)(((mBase + arow) * XS_STRIDE + ahalf * 8) * 2);

    float bestv[8], secondv[8];
    int   besti[8];
#pragma unroll
    for (int i = 0; i < 8; ++i) {
        bestv[i] = 3.402823466e38f; secondv[i] = 3.402823466e38f; besti[i] = 0;
    }

    float acc[4][4][4];
#pragma unroll
    for (int mt = 0; mt < 4; ++mt)
#pragma unroll
        for (int nt = 0; nt < 4; ++nt)
#pragma unroll
            for (int e = 0; e < 4; ++e) acc[mt][nt][e] = 0.f;

    auto loadPhi = [&](int buf, int colBase, int k0) {
#pragma unroll
        for (int t = 0; t < 2; ++t) {
            int c = tid + t * 256;
            int n = c >> 2, part = c & 3;
            size_t gOff = (size_t)(colBase + n) * DDIM + k0 + part * 8;
            unsigned sOff = (unsigned)((n * PS_STRIDE + part * 8) * 2);
            CP_ASYNC16(PsB + buf * PS_BYTES + sOff, &g_PhiH[gOff]);
            CP_ASYNC16(PsB + (2 + buf) * PS_BYTES + sOff, &g_PhiL[gOff]);
        }
        CP_COMMIT();
    };

    for (int ct = 0; ct < CDIM / 128; ++ct) {
        const int colBase = ct * 128;
        loadPhi(0, colBase, 0);
        for (int kc = 0; kc < 8; ++kc) {
            if (kc < 7) loadPhi((kc + 1) & 1, colBase, (kc + 1) * 32);
            if (kc < 7) { CP_WAIT1(); } else { CP_WAIT0(); }
            __syncthreads();
            const unsigned bufH = (unsigned)((kc & 1) * PS_BYTES);
            const unsigned bufL = (unsigned)((2 + (kc & 1)) * PS_BYTES);
            const int k0 = kc * 32;
#pragma unroll
            for (int ks = 0; ks < 2; ++ks) {
                unsigned ah[4][4], al[4][4];
#pragma unroll
                for (int mt = 0; mt < 4; ++mt) {
                    unsigned o = aOff + (unsigned)((mt * 16 * XS_STRIDE + k0 + ks * 16) * 2);
                    LDSM4(ah[mt][0], ah[mt][1], ah[mt][2], ah[mt][3], XhB + o);
                    LDSM4(al[mt][0], al[mt][1], al[mt][2], al[mt][3], XlB + o);
                }
                unsigned bh[4][2], bl[4][2];
#pragma unroll
                for (int nt2 = 0; nt2 < 2; ++nt2) {
                    unsigned o = (unsigned)(((nBase + nt2 * 16 + brow) * PS_STRIDE +
                                             ks * 16 + bhalf * 8) * 2);
                    LDSM4(bh[nt2 * 2][0], bh[nt2 * 2][1],
                          bh[nt2 * 2 + 1][0], bh[nt2 * 2 + 1][1], PsB + bufH + o);
                    LDSM4(bl[nt2 * 2][0], bl[nt2 * 2][1],
                          bl[nt2 * 2 + 1][0], bl[nt2 * 2 + 1][1], PsB + bufL + o);
                }
#pragma unroll
                for (int mt = 0; mt < 4; ++mt)
#pragma unroll
                    for (int nt = 0; nt < 4; ++nt) {
                        MMA16816(acc[mt][nt], ah[mt], bh[nt]);
                        MMA16816(acc[mt][nt], ah[mt], bl[nt]);
                        MMA16816(acc[mt][nt], al[mt], bh[nt]);
                    }
            }
            __syncthreads();
        }
        // Fold into running (best, second) — registers only.
#pragma unroll
        for (int nt = 0; nt < 4; ++nt) {
            int c0 = colBase + nBase + nt * 8 + (lane & 3) * 2;
            float p2a = __ldg(&g_p2[c0]);
            float p2b = __ldg(&g_p2[c0 + 1]);
#pragma unroll
            for (int mt = 0; mt < 4; ++mt) {
                float s[4];
                s[0] = fmaf(-2.f, acc[mt][nt][0], p2a);
                s[1] = fmaf(-2.f, acc[mt][nt][1], p2b);
                s[2] = fmaf(-2.f, acc[mt][nt][2], p2a);
                s[3] = fmaf(-2.f, acc[mt][nt][3], p2b);
#pragma unroll
                for (int e = 0; e < 4; ++e) {
                    int slot = mt * 2 + (e >> 1);
                    int c = c0 + (e & 1);
                    if (s[e] < bestv[slot]) {
                        secondv[slot] = bestv[slot];
                        bestv[slot] = s[e]; besti[slot] = c;
                    } else if (s[e] < secondv[slot]) {
                        secondv[slot] = s[e];
                    }
                    acc[mt][nt][e] = 0.f;
                }
            }
        }
    }

    // ---- Cross-thread reduction: 16 (best, idx, second) triples per row ----
    __syncthreads();
#pragma unroll
    for (int mt = 0; mt < 4; ++mt)
#pragma unroll
        for (int h = 0; h < 2; ++h) {
            int r = mBase + mt * 16 + (lane >> 2) + h * 8;
            red_v[r * 16 + wn * 4 + (lane & 3)] = bestv[mt * 2 + h];
            red_i[r * 16 + wn * 4 + (lane & 3)] = besti[mt * 2 + h];
            red_s[r * 16 + wn * 4 + (lane & 3)] = secondv[mt * 2 + h];
        }
    __syncthreads();

    if (tid < 128) {
        int gr = rowBase + tid;
        if (gr < NPTS) {
            float bv = red_v[tid * 16];
            int   bi = red_i[tid * 16];
            float sv = red_s[tid * 16];
#pragma unroll
            for (int t = 1; t < 16; ++t) {
                float v  = red_v[tid * 16 + t];
                int   ii = red_i[tid * 16 + t];
                float s2 = red_s[tid * 16 + t];
                if (v < bv || (v == bv && ii < bi)) {
                    sv = fminf(s2, bv);
                    bv = v; bi = ii;
                } else {
                    sv = fminf(sv, v);
                }
            }
            if (sv - bv < THRESH) {            // near-tie -> exact refinement
                int w = atomicAdd(&g_cnt, 1);
                g_list[w] = gr;
            }
            // fp32 ||x||^2 from global (row is L2-hot)
            const float4* xr = reinterpret_cast<const float4*>(&X[(size_t)gr * DDIM]);
            float x2 = 0.f;
#pragma unroll 8
            for (int t = 0; t < 64; ++t) {
                float4 v = xr[t];
                x2 += v.x * v.x + v.y * v.y + v.z * v.z + v.w * v.w;
            }
            float d2 = fmaxf(x2 + bv, 0.f);
            out[gr]        = (float)bi;
            out[NPTS + gr] = sqrtf(d2);
        }
    }
}

// ---------------------------------------------------------------------------
// Kernel 4: exact fp32 refinement of flagged points (R1 arithmetic).
// One block per flagged point; 256 threads x 4 centroids each.
// ---------------------------------------------------------------------------
__global__ __launch_bounds__(256) void refine_kernel(const float* __restrict__ X,
                                                     float* __restrict__ out) {
    __shared__ float xsh[DDIM];
    __shared__ float sv[256];
    __shared__ int   si[256];
    const int tid = threadIdx.x;
    const int nwork = g_cnt;

    for (int w = blockIdx.x; w < nwork; w += gridDim.x) {
        const int gr = g_list[w];
        if (tid < 64)
            *reinterpret_cast<float4*>(&xsh[tid * 4]) =
                *reinterpret_cast<const float4*>(&X[(size_t)gr * DDIM + tid * 4]);
        __syncthreads();

        float dot[4] = {0.f, 0.f, 0.f, 0.f};
        const float* p0 = &g_Phi[(size_t)tid * DDIM];
#pragma unroll 4
        for (int k = 0; k < DDIM; ++k) {
            float xv = xsh[k];
            dot[0] = fmaf(xv, p0[k],                  dot[0]);
            dot[1] = fmaf(xv, p0[256 * DDIM + k],     dot[1]);
            dot[2] = fmaf(xv, p0[512 * DDIM + k],     dot[2]);
            dot[3] = fmaf(xv, p0[768 * DDIM + k],     dot[3]);
        }
        float bv = 3.402823466e38f; int bi = 0;
#pragma unroll
        for (int q = 0; q < 4; ++q) {
            int c = tid + q * 256;
            float s = fmaf(-2.f, dot[q], g_p2[c]);
            if (s < bv) { bv = s; bi = c; }       // c strictly ascending per thread
        }
        sv[tid] = bv; si[tid] = bi;
        __syncthreads();
        for (int o = 128; o > 0; o >>= 1) {
            if (tid < o) {
                float v2 = sv[tid + o]; int i2 = si[tid + o];
                if (v2 < sv[tid] || (v2 == sv[tid] && i2 < si[tid])) {
                    sv[tid] = v2; si[tid] = i2;
                }
            }
            __syncthreads();
        }
        if (tid == 0) {
            const float4* xr = reinterpret_cast<const float4*>(&X[(size_t)gr * DDIM]);
            float x2 = 0.f;
#pragma unroll 8
            for (int t = 0; t < 64; ++t) {
                float4 v = xr[t];
                x2 += v.x * v.x + v.y * v.y + v.z * v.z + v.w * v.w;
            }
            float d2 = fmaxf(x2 + sv[0], 0.f);
            out[gr]        = (float)si[0];
            out[NPTS + gr] = sqrtf(d2);
        }
        __syncthreads();
    }
}

// ---------------------------------------------------------------------------
extern "C" void kernel_launch(void* const* d_in, const int* in_sizes, int n_in,
                              void* d_out, int out_size) {
    const float* X = (const float*)d_in[0];
    const float* parents = (const float*)d_in[1];
    const float* epsilon = (const float*)d_in[2];
    float* out = (float*)d_out;

    void* cntPtr = nullptr;
    cudaGetSymbolAddress(&cntPtr, g_cnt);
    cudaMemsetAsync(cntPtr, 0, sizeof(int));

    phi_kernel<<<dim3(DDIM / 32, CDIM / 64), 256>>>(parents, epsilon);
    p2_kernel<<<(CDIM * 32) / 256, 256>>>();

    static bool attrSet = false;   // idempotent attribute set (not a guard on work)
    if (!attrSet) {
        cudaFuncSetAttribute(dist_kernel, cudaFuncAttributeMaxDynamicSharedMemorySize,
                             SMEM_TOTAL);
        attrSet = true;
    }
    dist_kernel<<<(NPTS + 127) / 128, 256, SMEM_TOTAL>>>(X, out);
    refine_kernel<<<1024, 256>>>(X, out);
}

// round 7
// speedup vs baseline: 2.2500x; 1.1519x over previous
#include <cuda_runtime.h>
#include <cuda.h>
#include <cuda_bf16.h>
#include <math.h>

#define NPTS 100000
#define CDIM 1024
#define DDIM 256
#define THRESH 0.25f

// Scratch (no allocations allowed)
__device__ __align__(16) float g_Phi[CDIM * DDIM];
__device__ __align__(16) __nv_bfloat16 g_PhiH[CDIM * DDIM];
__device__ __align__(16) __nv_bfloat16 g_PhiL[CDIM * DDIM];
__device__ float g_p2[CDIM];
__device__ int g_cnt;
__device__ int g_list[NPTS];

// ---------------------------------------------------------------------------
// PTX helpers (sm_100-safe: mma.sync + TMA + mbarrier only, NO tcgen05)
// ---------------------------------------------------------------------------
static __device__ __forceinline__ unsigned smem_u32(const void* p) {
    return (unsigned)__cvta_generic_to_shared(p);
}
static __device__ __forceinline__ void split_bf16(float v, __nv_bfloat16& h,
                                                  __nv_bfloat16& l) {
    h = __float2bfloat16_rn(v);
    l = __float2bfloat16_rn(v - __bfloat162float(h));
}

#define SWZ128(off) ((off) ^ (((off) >> 3) & 0x70))

#define LDSM4(r0, r1, r2, r3, addr)                                            \
    asm volatile("ldmatrix.sync.aligned.m8n8.x4.shared.b16 {%0,%1,%2,%3}, [%4];" \
                 : "=r"(r0), "=r"(r1), "=r"(r2), "=r"(r3) : "r"(addr))

#define MMA16816(c, a, b)                                                      \
    asm volatile("mma.sync.aligned.m16n8k16.row.col.f32.bf16.bf16.f32 "        \
                 "{%0,%1,%2,%3}, {%4,%5,%6,%7}, {%8,%9}, {%0,%1,%2,%3};"       \
                 : "+f"((c)[0]), "+f"((c)[1]), "+f"((c)[2]), "+f"((c)[3])      \
                 : "r"((a)[0]), "r"((a)[1]), "r"((a)[2]), "r"((a)[3]),         \
                   "r"((b)[0]), "r"((b)[1]))

#define MBARRIER_INIT(mbar, cnt) \
    asm volatile("mbarrier.init.shared.b64 [%0], %1;" \
                 :: "r"((unsigned)(mbar)), "r"((unsigned)(cnt)) : "memory")
#define MBARRIER_EXPECT_TX(mbar, b) \
    asm volatile("mbarrier.arrive.expect_tx.shared.b64 _, [%0], %1;" \
                 :: "r"((unsigned)(mbar)), "r"((unsigned)(b)) : "memory")

static __device__ __forceinline__ void mbar_wait(unsigned mbar, unsigned parity) {
    asm volatile(
        "{\n\t"
        ".reg .pred P;\n\t"
        "W_%=:\n\t"
        "mbarrier.try_wait.parity.acquire.cta.shared::cta.b64 P, [%0], %1, 0x989680;\n\t"
        "@P bra D_%=;\n\t"
        "bra W_%=;\n\t"
        "D_%=:\n\t"
        "}"
        :: "r"(mbar), "r"(parity) : "memory");
}

static __device__ __forceinline__ void tma2d(unsigned dst, const CUtensorMap* map,
                                             int x, int y, unsigned mbar) {
    asm volatile(
        "cp.async.bulk.tensor.2d.shared::cta.global.tile.mbarrier::complete_tx::bytes "
        "[%0], [%1, {%2, %3}], [%4];"
        :: "r"(dst), "l"(map), "r"(x), "r"(y), "r"(mbar) : "memory");
}

// ---------------------------------------------------------------------------
// Kernel 1: Phi = parents @ epsilon. Sequential k 0..1023 per element (exact).
// ---------------------------------------------------------------------------
__global__ __launch_bounds__(256) void phi_kernel(const float* __restrict__ A,
                                                  const float* __restrict__ B) {
    __shared__ __align__(16) float As[16][64];
    __shared__ __align__(16) float Bs[16][36];
    const int tid = threadIdx.x;
    const int tx = tid & 15, ty = tid >> 4;
    const int m0 = blockIdx.y * 64;
    const int n0 = blockIdx.x * 32;
    float acc[4][2] = {};

    for (int k0 = 0; k0 < CDIM; k0 += 16) {
        __syncthreads();
        {
            int row = tid >> 2, c4 = tid & 3;
            float4 v = *reinterpret_cast<const float4*>(&A[(m0 + row) * CDIM + k0 + c4 * 4]);
            As[c4 * 4 + 0][row] = v.x;
            As[c4 * 4 + 1][row] = v.y;
            As[c4 * 4 + 2][row] = v.z;
            As[c4 * 4 + 3][row] = v.w;
        }
        if (tid < 128) {
            int row = tid >> 3, c8 = tid & 7;
            float4 v = *reinterpret_cast<const float4*>(&B[(k0 + row) * DDIM + n0 + c8 * 4]);
            Bs[row][c8 * 4 + 0] = v.x;
            Bs[row][c8 * 4 + 1] = v.y;
            Bs[row][c8 * 4 + 2] = v.z;
            Bs[row][c8 * 4 + 3] = v.w;
        }
        __syncthreads();
#pragma unroll
        for (int k = 0; k < 16; ++k) {
            float4 ra = *reinterpret_cast<const float4*>(&As[k][ty * 4]);
            float a[4] = {ra.x, ra.y, ra.z, ra.w};
            float b0 = Bs[k][tx * 2];
            float b1 = Bs[k][tx * 2 + 1];
#pragma unroll
            for (int i = 0; i < 4; ++i) {
                acc[i][0] = fmaf(a[i], b0, acc[i][0]);
                acc[i][1] = fmaf(a[i], b1, acc[i][1]);
            }
        }
    }
#pragma unroll
    for (int i = 0; i < 4; ++i) {
        float2 v = make_float2(acc[i][0], acc[i][1]);
        *reinterpret_cast<float2*>(&g_Phi[(m0 + ty * 4 + i) * DDIM + n0 + tx * 2]) = v;
    }
}

// ---------------------------------------------------------------------------
// Kernel 2: p2[c] = ||Phi_c||^2 (fp32) + hi/lo bf16 split of Phi.
// ---------------------------------------------------------------------------
__global__ __launch_bounds__(256) void p2_kernel() {
    int w = (blockIdx.x * blockDim.x + threadIdx.x) >> 5;
    int lane = threadIdx.x & 31;
    if (w >= CDIM) return;
    const float4* r = reinterpret_cast<const float4*>(&g_Phi[w * DDIM]);
    float4 a = r[lane];
    float4 b = r[lane + 32];
    __nv_bfloat16* dh = &g_PhiH[w * DDIM];
    __nv_bfloat16* dl = &g_PhiL[w * DDIM];
    float va[8] = {a.x, a.y, a.z, a.w, b.x, b.y, b.z, b.w};
    __nv_bfloat16 hh[8], ll[8];
#pragma unroll
    for (int i = 0; i < 8; ++i) split_bf16(va[i], hh[i], ll[i]);
#pragma unroll
    for (int i = 0; i < 4; ++i) {
        dh[lane * 4 + i]       = hh[i];
        dl[lane * 4 + i]       = ll[i];
        dh[128 + lane * 4 + i] = hh[4 + i];
        dl[128 + lane * 4 + i] = ll[4 + i];
    }
    float s = a.x * a.x + a.y * a.y + a.z * a.z + a.w * a.w
            + b.x * b.x + b.y * b.y + b.z * b.z + b.w * b.w;
#pragma unroll
    for (int o = 16; o > 0; o >>= 1)
        s += __shfl_xor_sync(0xFFFFFFFFu, s, o);
    if (lane == 0) g_p2[w] = s;
}

// ---------------------------------------------------------------------------
// Kernel 3: split-bf16 mma.sync dots + argmin; Phi streamed via TMA (SW128).
// SMEM: [0..16) 2 mbarriers | X_OFF Xh[128][264] | XL_OFF Xl | STG_OFF 2 stages
// x (PhiH 16KB + PhiL 16KB, SW128 [128 rows][64 k]) | P2_OFF p2 | red aliases
// ---------------------------------------------------------------------------
#define XS_STRIDE 264
#define XS_BYTES  (128 * XS_STRIDE * 2)          // 67584
#define X_OFF     1024
#define XL_OFF    (X_OFF + XS_BYTES)             // 68608
#define STG_OFF   (XL_OFF + XS_BYTES)            // 136192 (1024-aligned)
#define P2_OFF    (STG_OFF + 2 * 32768)          // 201728
#define SMEM_TOTAL (P2_OFF + 4096)               // 205824

__global__ __launch_bounds__(256, 1)
void dist_kernel(const float* __restrict__ X, float* __restrict__ out,
                 const __grid_constant__ CUtensorMap tmapH,
                 const __grid_constant__ CUtensorMap tmapL) {
    extern __shared__ __align__(1024) char smem[];
    const unsigned SB = smem_u32(smem);
    __nv_bfloat16* Xh = reinterpret_cast<__nv_bfloat16*>(smem + X_OFF);
    __nv_bfloat16* Xl = reinterpret_cast<__nv_bfloat16*>(smem + XL_OFF);
    float* p2s = reinterpret_cast<float*>(smem + P2_OFF);
    // Reduction arrays alias the TMA stage buffers (used only after mainloop).
    float* red_v = reinterpret_cast<float*>(smem + STG_OFF);
    int*   red_i = reinterpret_cast<int*>(smem + STG_OFF + 8192);
    float* red_s = reinterpret_cast<float*>(smem + STG_OFF + 16384);

    const int tid = threadIdx.x;
    const int lane = tid & 31, wid = tid >> 5;
    const int wm = wid >> 2, wn = wid & 3;
    const int mBase = wm * 64, nBase = wn * 32;
    const int rowBase = blockIdx.x * 128;

    if (tid == 0) {
        MBARRIER_INIT(SB + 0, 1);     // full[0]
        MBARRIER_INIT(SB + 8, 1);     // full[1]
    }

    // ---- X tile fill: fp32 -> hi/lo bf16, padded-linear (R5 layout) ----
    for (int i = tid; i < 128 * 64; i += 256) {
        int r = i >> 6, q = i & 63;
        int gr = rowBase + r;
        float4 v = make_float4(0.f, 0.f, 0.f, 0.f);
        if (gr < NPTS)
            v = *reinterpret_cast<const float4*>(&X[(size_t)gr * DDIM + q * 4]);
        float va[4] = {v.x, v.y, v.z, v.w};
        __nv_bfloat16 hh[4], ll[4];
#pragma unroll
        for (int t = 0; t < 4; ++t) split_bf16(va[t], hh[t], ll[t]);
        *reinterpret_cast<__nv_bfloat162*>(&Xh[r * XS_STRIDE + q * 4]) =
            __nv_bfloat162(hh[0], hh[1]);
        *reinterpret_cast<__nv_bfloat162*>(&Xh[r * XS_STRIDE + q * 4 + 2]) =
            __nv_bfloat162(hh[2], hh[3]);
        *reinterpret_cast<__nv_bfloat162*>(&Xl[r * XS_STRIDE + q * 4]) =
            __nv_bfloat162(ll[0], ll[1]);
        *reinterpret_cast<__nv_bfloat162*>(&Xl[r * XS_STRIDE + q * 4 + 2]) =
            __nv_bfloat162(ll[2], ll[3]);
    }
    for (int i = tid; i < CDIM; i += 256) p2s[i] = g_p2[i];
    __syncthreads();

    // Prologue: stages 0 and 1
    if (tid == 0) {
#pragma unroll
        for (int g = 0; g < 2; ++g) {
            unsigned mb = SB + (unsigned)g * 8;
            unsigned dst = SB + STG_OFF + (unsigned)g * 32768;
            MBARRIER_EXPECT_TX(mb, 32768);
            tma2d(dst,         &tmapH, (g & 3) * 64, (g >> 2) * 128, mb);
            tma2d(dst + 16384, &tmapL, (g & 3) * 64, (g >> 2) * 128, mb);
        }
    }

    // ldmatrix lane addressing (identical to R5)
    const int arow = lane & 15;
    const int ahalf = lane >> 4;
    const int brow = (lane & 7) | ((lane >> 1) & 8);
    const int bhalf = (lane >> 3) & 1;

    const unsigned XhB = smem_u32(Xh);
    const unsigned XlB = smem_u32(Xl);
    const unsigned aOff = (unsigned)(((mBase + arow) * XS_STRIDE + ahalf * 8) * 2);

    float bestv[8], secondv[8];
    int   besti[8];
#pragma unroll
    for (int i = 0; i < 8; ++i) {
        bestv[i] = 3.402823466e38f; secondv[i] = 3.402823466e38f; besti[i] = 0;
    }

    float acc[4][4][4];
#pragma unroll
    for (int mt = 0; mt < 4; ++mt)
#pragma unroll
        for (int nt = 0; nt < 4; ++nt)
#pragma unroll
            for (int e = 0; e < 4; ++e) acc[mt][nt][e] = 0.f;

    for (int g = 0; g < 32; ++g) {                   // g = ct*4 + kc
        const int s = g & 1;
        const int kc = g & 3;
        mbar_wait(SB + (unsigned)s * 8, (unsigned)((g >> 1) & 1));
        const unsigned stH = SB + STG_OFF + (unsigned)s * 32768;
#pragma unroll
        for (int ks = 0; ks < 4; ++ks) {             // k16 steps within 64-chunk
            unsigned ah[4][4], al[4][4];
#pragma unroll
            for (int mt = 0; mt < 4; ++mt) {
                unsigned o = aOff + (unsigned)((mt * 16 * XS_STRIDE + kc * 64 + ks * 16) * 2);
                LDSM4(ah[mt][0], ah[mt][1], ah[mt][2], ah[mt][3], XhB + o);
                LDSM4(al[mt][0], al[mt][1], al[mt][2], al[mt][3], XlB + o);
            }
            unsigned bh[4][2], bl[4][2];
#pragma unroll
            for (int nt2 = 0; nt2 < 2; ++nt2) {
                unsigned off = (unsigned)((nBase + nt2 * 16 + brow) * 128 +
                                          ks * 32 + bhalf * 16);
                off = SWZ128(off);
                LDSM4(bh[nt2 * 2][0], bh[nt2 * 2][1],
                      bh[nt2 * 2 + 1][0], bh[nt2 * 2 + 1][1], stH + off);
                LDSM4(bl[nt2 * 2][0], bl[nt2 * 2][1],
                      bl[nt2 * 2 + 1][0], bl[nt2 * 2 + 1][1], stH + 16384 + off);
            }
#pragma unroll
            for (int mt = 0; mt < 4; ++mt)
#pragma unroll
                for (int nt = 0; nt < 4; ++nt) {
                    MMA16816(acc[mt][nt], ah[mt], bh[nt]);
                    MMA16816(acc[mt][nt], ah[mt], bl[nt]);
                    MMA16816(acc[mt][nt], al[mt], bh[nt]);
                }
        }
        __syncthreads();                             // stage s fully consumed
        if (tid == 0 && g + 2 < 32) {
            int g2 = g + 2;
            unsigned mb = SB + (unsigned)s * 8;
            unsigned dst = SB + STG_OFF + (unsigned)s * 32768;
            MBARRIER_EXPECT_TX(mb, 32768);
            tma2d(dst,         &tmapH, (g2 & 3) * 64, (g2 >> 2) * 128, mb);
            tma2d(dst + 16384, &tmapL, (g2 & 3) * 64, (g2 >> 2) * 128, mb);
        }
        if (kc == 3) {                               // full K done: fold argmin
            const int colBase = (g >> 2) * 128;
#pragma unroll
            for (int nt = 0; nt < 4; ++nt) {
                int c0 = colBase + nBase + nt * 8 + (lane & 3) * 2;
                float p2a = p2s[c0];
                float p2b = p2s[c0 + 1];
#pragma unroll
                for (int mt = 0; mt < 4; ++mt) {
                    float sc[4];
                    sc[0] = fmaf(-2.f, acc[mt][nt][0], p2a);
                    sc[1] = fmaf(-2.f, acc[mt][nt][1], p2b);
                    sc[2] = fmaf(-2.f, acc[mt][nt][2], p2a);
                    sc[3] = fmaf(-2.f, acc[mt][nt][3], p2b);
#pragma unroll
                    for (int e = 0; e < 4; ++e) {
                        int slot = mt * 2 + (e >> 1);
                        int c = c0 + (e & 1);
                        if (sc[e] < bestv[slot]) {
                            secondv[slot] = bestv[slot];
                            bestv[slot] = sc[e]; besti[slot] = c;
                        } else if (sc[e] < secondv[slot]) {
                            secondv[slot] = sc[e];
                        }
                        acc[mt][nt][e] = 0.f;
                    }
                }
            }
        }
    }

    // ---- Cross-thread reduction: 16 (best, idx, second) triples per row ----
    __syncthreads();   // stage buffers now reused as red arrays
#pragma unroll
    for (int mt = 0; mt < 4; ++mt)
#pragma unroll
        for (int h = 0; h < 2; ++h) {
            int r = mBase + mt * 16 + (lane >> 2) + h * 8;
            red_v[r * 16 + wn * 4 + (lane & 3)] = bestv[mt * 2 + h];
            red_i[r * 16 + wn * 4 + (lane & 3)] = besti[mt * 2 + h];
            red_s[r * 16 + wn * 4 + (lane & 3)] = secondv[mt * 2 + h];
        }
    __syncthreads();

    if (tid < 128) {
        int gr = rowBase + tid;
        if (gr < NPTS) {
            float bv = red_v[tid * 16];
            int   bi = red_i[tid * 16];
            float sv = red_s[tid * 16];
#pragma unroll
            for (int t = 1; t < 16; ++t) {
                float v  = red_v[tid * 16 + t];
                int   ii = red_i[tid * 16 + t];
                float s2 = red_s[tid * 16 + t];
                if (v < bv || (v == bv && ii < bi)) {
                    sv = fminf(s2, bv);
                    bv = v; bi = ii;
                } else {
                    sv = fminf(sv, v);
                }
            }
            if (sv - bv < THRESH) {            // near-tie -> exact refinement
                int w = atomicAdd(&g_cnt, 1);
                g_list[w] = gr;
            }
            const float4* xr = reinterpret_cast<const float4*>(&X[(size_t)gr * DDIM]);
            float x2 = 0.f;
#pragma unroll 8
            for (int t = 0; t < 64; ++t) {
                float4 v = xr[t];
                x2 += v.x * v.x + v.y * v.y + v.z * v.z + v.w * v.w;
            }
            float d2 = fmaxf(x2 + bv, 0.f);
            out[gr]        = (float)bi;
            out[NPTS + gr] = sqrtf(d2);
        }
    }
}

// ---------------------------------------------------------------------------
// Kernel 4: exact fp32 refinement of flagged points (reference arithmetic).
// ---------------------------------------------------------------------------
__global__ __launch_bounds__(256) void refine_kernel(const float* __restrict__ X,
                                                     float* __restrict__ out) {
    __shared__ float xsh[DDIM];
    __shared__ float sv[256];
    __shared__ int   si[256];
    const int tid = threadIdx.x;
    const int nwork = g_cnt;

    for (int w = blockIdx.x; w < nwork; w += gridDim.x) {
        const int gr = g_list[w];
        if (tid < 64)
            *reinterpret_cast<float4*>(&xsh[tid * 4]) =
                *reinterpret_cast<const float4*>(&X[(size_t)gr * DDIM + tid * 4]);
        __syncthreads();

        float dot[4] = {0.f, 0.f, 0.f, 0.f};
        const float* p0 = &g_Phi[(size_t)tid * DDIM];
#pragma unroll 4
        for (int k = 0; k < DDIM; ++k) {
            float xv = xsh[k];
            dot[0] = fmaf(xv, p0[k],              dot[0]);
            dot[1] = fmaf(xv, p0[256 * DDIM + k], dot[1]);
            dot[2] = fmaf(xv, p0[512 * DDIM + k], dot[2]);
            dot[3] = fmaf(xv, p0[768 * DDIM + k], dot[3]);
        }
        float bv = 3.402823466e38f; int bi = 0;
#pragma unroll
        for (int q = 0; q < 4; ++q) {
            int c = tid + q * 256;
            float s = fmaf(-2.f, dot[q], g_p2[c]);
            if (s < bv) { bv = s; bi = c; }
        }
        sv[tid] = bv; si[tid] = bi;
        __syncthreads();
        for (int o = 128; o > 0; o >>= 1) {
            if (tid < o) {
                float v2 = sv[tid + o]; int i2 = si[tid + o];
                if (v2 < sv[tid] || (v2 == sv[tid] && i2 < si[tid])) {
                    sv[tid] = v2; si[tid] = i2;
                }
            }
            __syncthreads();
        }
        if (tid == 0) {
            const float4* xr = reinterpret_cast<const float4*>(&X[(size_t)gr * DDIM]);
            float x2 = 0.f;
#pragma unroll 8
            for (int q = 0; q < 64; ++q) {
                float4 v = xr[q];
                x2 += v.x * v.x + v.y * v.y + v.z * v.z + v.w * v.w;
            }
            float d2 = fmaxf(x2 + sv[0], 0.f);
            out[gr]        = (float)si[0];
            out[NPTS + gr] = sqrtf(d2);
        }
        __syncthreads();
    }
}

// ---------------------------------------------------------------------------
// Host launcher
// ---------------------------------------------------------------------------
typedef CUresult (*PFN_tmapEncode)(
    CUtensorMap*, CUtensorMapDataType, cuuint32_t, void*,
    const cuuint64_t*, const cuuint64_t*, const cuuint32_t*, const cuuint32_t*,
    CUtensorMapInterleave, CUtensorMapSwizzle, CUtensorMapL2promotion,
    CUtensorMapFloatOOBfill);

static PFN_tmapEncode get_encode_fn() {
    static PFN_tmapEncode fn = nullptr;
    if (!fn) {
        void* p = nullptr;
        cudaDriverEntryPointQueryResult st;
        cudaGetDriverEntryPointByVersion("cuTensorMapEncodeTiled", &p, 12000,
                                         cudaEnableDefault, &st);
        fn = (PFN_tmapEncode)p;
    }
    return fn;
}

static void make_phi_map(CUtensorMap* map, void* ptr) {
    cuuint64_t dims[2]    = {DDIM, CDIM};           // inner = k, outer = rows
    cuuint64_t strides[1] = {DDIM * 2};             // 512 B per row
    cuuint32_t box[2]     = {64, 128};              // 128B x 128 rows (SW128)
    cuuint32_t es[2]      = {1, 1};
    get_encode_fn()(map, CU_TENSOR_MAP_DATA_TYPE_BFLOAT16, 2, ptr,
                    dims, strides, box, es,
                    CU_TENSOR_MAP_INTERLEAVE_NONE, CU_TENSOR_MAP_SWIZZLE_128B,
                    CU_TENSOR_MAP_L2_PROMOTION_L2_128B,
                    CU_TENSOR_MAP_FLOAT_OOB_FILL_NONE);
}

extern "C" void kernel_launch(void* const* d_in, const int* in_sizes, int n_in,
                              void* d_out, int out_size) {
    const float* X = (const float*)d_in[0];
    const float* parents = (const float*)d_in[1];
    const float* epsilon = (const float*)d_in[2];
    float* out = (float*)d_out;

    void* cntPtr = nullptr;
    cudaGetSymbolAddress(&cntPtr, g_cnt);
    cudaMemsetAsync(cntPtr, 0, sizeof(int));

    void* phiH = nullptr; void* phiL = nullptr;
    cudaGetSymbolAddress(&phiH, g_PhiH);
    cudaGetSymbolAddress(&phiL, g_PhiL);
    CUtensorMap tmapH, tmapL;
    make_phi_map(&tmapH, phiH);
    make_phi_map(&tmapL, phiL);

    phi_kernel<<<dim3(DDIM / 32, CDIM / 64), 256>>>(parents, epsilon);
    p2_kernel<<<(CDIM * 32) / 256, 256>>>();

    static bool attrSet = false;   // idempotent attribute set (not a guard on work)
    if (!attrSet) {
        cudaFuncSetAttribute(dist_kernel, cudaFuncAttributeMaxDynamicSharedMemorySize,
                             SMEM_TOTAL);
        attrSet = true;
    }
    dist_kernel<<<(NPTS + 127) / 128, 256, SMEM_TOTAL>>>(X, out, tmapH, tmapL);
    refine_kernel<<<1024, 256>>>(X, out);
}

// round 8
// speedup vs baseline: 3.1683x; 1.4081x over previous
#include <cuda_runtime.h>
#include <cuda.h>
#include <cuda_fp16.h>
#include <math.h>

#define NPTS 100000
#define CDIM 1024
#define DDIM 256
#define THRESH 8.0f

// Scratch (no allocations allowed)
__device__ __align__(16) float g_Phi[CDIM * DDIM];
__device__ __align__(16) __half g_PhiH[CDIM * DDIM];
__device__ float g_p2[CDIM];
__device__ int g_cnt;
__device__ int g_list[NPTS];

// ---------------------------------------------------------------------------
// PTX helpers (sm_100-safe: mma.sync + TMA + mbarrier only)
// ---------------------------------------------------------------------------
static __device__ __forceinline__ unsigned smem_u32(const void* p) {
    return (unsigned)__cvta_generic_to_shared(p);
}

#define SWZ128(off) ((off) ^ (((off) >> 3) & 0x70))

#define LDSM4(r0, r1, r2, r3, addr)                                            \
    asm volatile("ldmatrix.sync.aligned.m8n8.x4.shared.b16 {%0,%1,%2,%3}, [%4];" \
                 : "=r"(r0), "=r"(r1), "=r"(r2), "=r"(r3) : "r"(addr))

#define MMA16816F16(c, a, b)                                                   \
    asm volatile("mma.sync.aligned.m16n8k16.row.col.f32.f16.f16.f32 "          \
                 "{%0,%1,%2,%3}, {%4,%5,%6,%7}, {%8,%9}, {%0,%1,%2,%3};"       \
                 : "+f"((c)[0]), "+f"((c)[1]), "+f"((c)[2]), "+f"((c)[3])      \
                 : "r"((a)[0]), "r"((a)[1]), "r"((a)[2]), "r"((a)[3]),         \
                   "r"((b)[0]), "r"((b)[1]))

#define MBARRIER_INIT(mbar, cnt) \
    asm volatile("mbarrier.init.shared.b64 [%0], %1;" \
                 :: "r"((unsigned)(mbar)), "r"((unsigned)(cnt)) : "memory")
#define MBARRIER_EXPECT_TX(mbar, b) \
    asm volatile("mbarrier.arrive.expect_tx.shared.b64 _, [%0], %1;" \
                 :: "r"((unsigned)(mbar)), "r"((unsigned)(b)) : "memory")

static __device__ __forceinline__ void mbar_wait(unsigned mbar, unsigned parity) {
    asm volatile(
        "{\n\t"
        ".reg .pred P;\n\t"
        "W_%=:\n\t"
        "mbarrier.try_wait.parity.acquire.cta.shared::cta.b64 P, [%0], %1, 0x989680;\n\t"
        "@P bra D_%=;\n\t"
        "bra W_%=;\n\t"
        "D_%=:\n\t"
        "}"
        :: "r"(mbar), "r"(parity) : "memory");
}

static __device__ __forceinline__ void tma2d(unsigned dst, const CUtensorMap* map,
                                             int x, int y, unsigned mbar) {
    asm volatile(
        "cp.async.bulk.tensor.2d.shared::cta.global.tile.mbarrier::complete_tx::bytes "
        "[%0], [%1, {%2, %3}], [%4];"
        :: "r"(dst), "l"(map), "r"(x), "r"(y), "r"(mbar) : "memory");
}

// ---------------------------------------------------------------------------
// Kernel 1: Phi = parents @ epsilon. Sequential k 0..1023 per element (exact).
// ---------------------------------------------------------------------------
__global__ __launch_bounds__(256) void phi_kernel(const float* __restrict__ A,
                                                  const float* __restrict__ B) {
    __shared__ __align__(16) float As[16][64];
    __shared__ __align__(16) float Bs[16][36];
    const int tid = threadIdx.x;
    const int tx = tid & 15, ty = tid >> 4;
    const int m0 = blockIdx.y * 64;
    const int n0 = blockIdx.x * 32;
    float acc[4][2] = {};

    for (int k0 = 0; k0 < CDIM; k0 += 16) {
        __syncthreads();
        {
            int row = tid >> 2, c4 = tid & 3;
            float4 v = *reinterpret_cast<const float4*>(&A[(m0 + row) * CDIM + k0 + c4 * 4]);
            As[c4 * 4 + 0][row] = v.x;
            As[c4 * 4 + 1][row] = v.y;
            As[c4 * 4 + 2][row] = v.z;
            As[c4 * 4 + 3][row] = v.w;
        }
        if (tid < 128) {
            int row = tid >> 3, c8 = tid & 7;
            float4 v = *reinterpret_cast<const float4*>(&B[(k0 + row) * DDIM + n0 + c8 * 4]);
            Bs[row][c8 * 4 + 0] = v.x;
            Bs[row][c8 * 4 + 1] = v.y;
            Bs[row][c8 * 4 + 2] = v.z;
            Bs[row][c8 * 4 + 3] = v.w;
        }
        __syncthreads();
#pragma unroll
        for (int k = 0; k < 16; ++k) {
            float4 ra = *reinterpret_cast<const float4*>(&As[k][ty * 4]);
            float a[4] = {ra.x, ra.y, ra.z, ra.w};
            float b0 = Bs[k][tx * 2];
            float b1 = Bs[k][tx * 2 + 1];
#pragma unroll
            for (int i = 0; i < 4; ++i) {
                acc[i][0] = fmaf(a[i], b0, acc[i][0]);
                acc[i][1] = fmaf(a[i], b1, acc[i][1]);
            }
        }
    }
#pragma unroll
    for (int i = 0; i < 4; ++i) {
        float2 v = make_float2(acc[i][0], acc[i][1]);
        *reinterpret_cast<float2*>(&g_Phi[(m0 + ty * 4 + i) * DDIM + n0 + tx * 2]) = v;
    }
}

// ---------------------------------------------------------------------------
// Kernel 2: p2[c] = ||Phi_c||^2 (fp32) + fp16 copy of Phi.
// ---------------------------------------------------------------------------
__global__ __launch_bounds__(256) void p2_kernel() {
    int w = (blockIdx.x * blockDim.x + threadIdx.x) >> 5;
    int lane = threadIdx.x & 31;
    if (w >= CDIM) return;
    const float4* r = reinterpret_cast<const float4*>(&g_Phi[w * DDIM]);
    float4 a = r[lane];
    float4 b = r[lane + 32];
    __half* dh = &g_PhiH[w * DDIM];
    {
        __half2 h0 = __floats2half2_rn(a.x, a.y);
        __half2 h1 = __floats2half2_rn(a.z, a.w);
        *reinterpret_cast<__half2*>(&dh[lane * 4])     = h0;
        *reinterpret_cast<__half2*>(&dh[lane * 4 + 2]) = h1;
        __half2 h2 = __floats2half2_rn(b.x, b.y);
        __half2 h3 = __floats2half2_rn(b.z, b.w);
        *reinterpret_cast<__half2*>(&dh[128 + lane * 4])     = h2;
        *reinterpret_cast<__half2*>(&dh[128 + lane * 4 + 2]) = h3;
    }
    float s = a.x * a.x + a.y * a.y + a.z * a.z + a.w * a.w
            + b.x * b.x + b.y * b.y + b.z * b.z + b.w * b.w;
#pragma unroll
    for (int o = 16; o > 0; o >>= 1)
        s += __shfl_xor_sync(0xFFFFFFFFu, s, o);
    if (lane == 0) g_p2[w] = s;
}

// ---------------------------------------------------------------------------
// Kernel 3: single-pass fp16 mma.sync dots + argmin; Phi via TMA (SW128).
// SMEM: [0..16) mbarriers | X_OFF Xh[128][264] fp16 | STG_OFF 2x16KB stages |
// P2_OFF p2 | red arrays alias stages after mainloop.  2 CTAs/SM.
// ---------------------------------------------------------------------------
#define XS_STRIDE 264
#define XS_BYTES  (128 * XS_STRIDE * 2)          // 67584
#define X_OFF     1024
#define STG_OFF   (X_OFF + XS_BYTES)             // 68608 (1024-aligned)
#define P2_OFF    (STG_OFF + 2 * 16384)          // 101376
#define SMEM_TOTAL (P2_OFF + 4096)               // 105472

__global__ __launch_bounds__(256, 2)
void dist_kernel(const float* __restrict__ X, float* __restrict__ out,
                 const __grid_constant__ CUtensorMap tmapH) {
    extern __shared__ __align__(1024) char smem[];
    const unsigned SB = smem_u32(smem);
    __half* Xh = reinterpret_cast<__half*>(smem + X_OFF);
    float* p2s = reinterpret_cast<float*>(smem + P2_OFF);
    // Reduction arrays alias the TMA stage buffers (used only after mainloop).
    float* red_v = reinterpret_cast<float*>(smem + STG_OFF);
    int*   red_i = reinterpret_cast<int*>(smem + STG_OFF + 8192);
    float* red_s = reinterpret_cast<float*>(smem + STG_OFF + 16384);

    const int tid = threadIdx.x;
    const int lane = tid & 31, wid = tid >> 5;
    const int wm = wid >> 2, wn = wid & 3;
    const int mBase = wm * 64, nBase = wn * 32;
    const int rowBase = blockIdx.x * 128;

    if (tid == 0) {
        MBARRIER_INIT(SB + 0, 1);     // full[0]
        MBARRIER_INIT(SB + 8, 1);     // full[1]
    }

    // ---- X tile fill: fp32 -> fp16, padded-linear ----
    for (int i = tid; i < 128 * 64; i += 256) {
        int r = i >> 6, q = i & 63;
        int gr = rowBase + r;
        float4 v = make_float4(0.f, 0.f, 0.f, 0.f);
        if (gr < NPTS)
            v = *reinterpret_cast<const float4*>(&X[(size_t)gr * DDIM + q * 4]);
        *reinterpret_cast<__half2*>(&Xh[r * XS_STRIDE + q * 4]) =
            __floats2half2_rn(v.x, v.y);
        *reinterpret_cast<__half2*>(&Xh[r * XS_STRIDE + q * 4 + 2]) =
            __floats2half2_rn(v.z, v.w);
    }
    for (int i = tid; i < CDIM; i += 256) p2s[i] = g_p2[i];
    __syncthreads();

    // Prologue: stages 0 and 1
    if (tid == 0) {
#pragma unroll
        for (int g = 0; g < 2; ++g) {
            unsigned mb = SB + (unsigned)g * 8;
            unsigned dst = SB + STG_OFF + (unsigned)g * 16384;
            MBARRIER_EXPECT_TX(mb, 16384);
            tma2d(dst, &tmapH, (g & 3) * 64, (g >> 2) * 128, mb);
        }
    }

    // ldmatrix lane addressing
    const int arow = lane & 15;
    const int ahalf = lane >> 4;
    const int brow = (lane & 7) | ((lane >> 1) & 8);
    const int bhalf = (lane >> 3) & 1;

    const unsigned XhB = smem_u32(Xh);
    const unsigned aOff = (unsigned)(((mBase + arow) * XS_STRIDE + ahalf * 8) * 2);

    float bestv[8], secondv[8];
    int   besti[8];
#pragma unroll
    for (int i = 0; i < 8; ++i) {
        bestv[i] = 3.402823466e38f; secondv[i] = 3.402823466e38f; besti[i] = 0;
    }

    float acc[4][4][4];
#pragma unroll
    for (int mt = 0; mt < 4; ++mt)
#pragma unroll
        for (int nt = 0; nt < 4; ++nt)
#pragma unroll
            for (int e = 0; e < 4; ++e) acc[mt][nt][e] = 0.f;

    for (int g = 0; g < 32; ++g) {                   // g = ct*4 + kc
        const int s = g & 1;
        const int kc = g & 3;
        mbar_wait(SB + (unsigned)s * 8, (unsigned)((g >> 1) & 1));
        const unsigned stH = SB + STG_OFF + (unsigned)s * 16384;
#pragma unroll
        for (int ks = 0; ks < 4; ++ks) {             // k16 steps within 64-chunk
            unsigned ah[4][4];
#pragma unroll
            for (int mt = 0; mt < 4; ++mt) {
                unsigned o = aOff + (unsigned)((mt * 16 * XS_STRIDE + kc * 64 + ks * 16) * 2);
                LDSM4(ah[mt][0], ah[mt][1], ah[mt][2], ah[mt][3], XhB + o);
            }
            unsigned bh[4][2];
#pragma unroll
            for (int nt2 = 0; nt2 < 2; ++nt2) {
                unsigned off = (unsigned)((nBase + nt2 * 16 + brow) * 128 +
                                          ks * 32 + bhalf * 16);
                off = SWZ128(off);
                LDSM4(bh[nt2 * 2][0], bh[nt2 * 2][1],
                      bh[nt2 * 2 + 1][0], bh[nt2 * 2 + 1][1], stH + off);
            }
#pragma unroll
            for (int mt = 0; mt < 4; ++mt)
#pragma unroll
                for (int nt = 0; nt < 4; ++nt)
                    MMA16816F16(acc[mt][nt], ah[mt], bh[nt]);
        }
        __syncthreads();                             // stage s fully consumed
        if (tid == 0 && g + 2 < 32) {
            int g2 = g + 2;
            unsigned mb = SB + (unsigned)s * 8;
            unsigned dst = SB + STG_OFF + (unsigned)s * 16384;
            MBARRIER_EXPECT_TX(mb, 16384);
            tma2d(dst, &tmapH, (g2 & 3) * 64, (g2 >> 2) * 128, mb);
        }
        if (kc == 3) {                               // full K done: fold argmin
            const int colBase = (g >> 2) * 128;
#pragma unroll
            for (int nt = 0; nt < 4; ++nt) {
                int c0 = colBase + nBase + nt * 8 + (lane & 3) * 2;
                float p2a = p2s[c0];
                float p2b = p2s[c0 + 1];
#pragma unroll
                for (int mt = 0; mt < 4; ++mt) {
                    float sc[4];
                    sc[0] = fmaf(-2.f, acc[mt][nt][0], p2a);
                    sc[1] = fmaf(-2.f, acc[mt][nt][1], p2b);
                    sc[2] = fmaf(-2.f, acc[mt][nt][2], p2a);
                    sc[3] = fmaf(-2.f, acc[mt][nt][3], p2b);
#pragma unroll
                    for (int e = 0; e < 4; ++e) {
                        int slot = mt * 2 + (e >> 1);
                        int c = c0 + (e & 1);
                        if (sc[e] < bestv[slot]) {
                            secondv[slot] = bestv[slot];
                            bestv[slot] = sc[e]; besti[slot] = c;
                        } else if (sc[e] < secondv[slot]) {
                            secondv[slot] = sc[e];
                        }
                        acc[mt][nt][e] = 0.f;
                    }
                }
            }
        }
    }

    // ---- Cross-thread reduction: 16 (best, idx, second) triples per row ----
    __syncthreads();   // stage buffers now reused as red arrays
#pragma unroll
    for (int mt = 0; mt < 4; ++mt)
#pragma unroll
        for (int h = 0; h < 2; ++h) {
            int r = mBase + mt * 16 + (lane >> 2) + h * 8;
            red_v[r * 16 + wn * 4 + (lane & 3)] = bestv[mt * 2 + h];
            red_i[r * 16 + wn * 4 + (lane & 3)] = besti[mt * 2 + h];
            red_s[r * 16 + wn * 4 + (lane & 3)] = secondv[mt * 2 + h];
        }
    __syncthreads();

    if (tid < 128) {
        int gr = rowBase + tid;
        if (gr < NPTS) {
            float bv = red_v[tid * 16];
            int   bi = red_i[tid * 16];
            float sv = red_s[tid * 16];
#pragma unroll
            for (int t = 1; t < 16; ++t) {
                float v  = red_v[tid * 16 + t];
                int   ii = red_i[tid * 16 + t];
                float s2 = red_s[tid * 16 + t];
                if (v < bv || (v == bv && ii < bi)) {
                    sv = fminf(s2, bv);
                    bv = v; bi = ii;
                } else {
                    sv = fminf(sv, v);
                }
            }
            if (sv - bv < THRESH) {            // near-tie -> exact refinement
                int w = atomicAdd(&g_cnt, 1);
                g_list[w] = gr;
            }
            const float4* xr = reinterpret_cast<const float4*>(&X[(size_t)gr * DDIM]);
            float x2 = 0.f;
#pragma unroll 8
            for (int t = 0; t < 64; ++t) {
                float4 v = xr[t];
                x2 += v.x * v.x + v.y * v.y + v.z * v.z + v.w * v.w;
            }
            float d2 = fmaxf(x2 + bv, 0.f);
            out[gr]        = (float)bi;
            out[NPTS + gr] = sqrtf(d2);
        }
    }
}

// ---------------------------------------------------------------------------
// Kernel 4: exact fp32 refinement of flagged points (reference arithmetic).
// ---------------------------------------------------------------------------
__global__ __launch_bounds__(256) void refine_kernel(const float* __restrict__ X,
                                                     float* __restrict__ out) {
    __shared__ float xsh[DDIM];
    __shared__ float sv[256];
    __shared__ int   si[256];
    const int tid = threadIdx.x;
    const int nwork = g_cnt;

    for (int w = blockIdx.x; w < nwork; w += gridDim.x) {
        const int gr = g_list[w];
        if (tid < 64)
            *reinterpret_cast<float4*>(&xsh[tid * 4]) =
                *reinterpret_cast<const float4*>(&X[(size_t)gr * DDIM + tid * 4]);
        __syncthreads();

        float dot[4] = {0.f, 0.f, 0.f, 0.f};
        const float* p0 = &g_Phi[(size_t)tid * DDIM];
#pragma unroll 4
        for (int k = 0; k < DDIM; ++k) {
            float xv = xsh[k];
            dot[0] = fmaf(xv, p0[k],              dot[0]);
            dot[1] = fmaf(xv, p0[256 * DDIM + k], dot[1]);
            dot[2] = fmaf(xv, p0[512 * DDIM + k], dot[2]);
            dot[3] = fmaf(xv, p0[768 * DDIM + k], dot[3]);
        }
        float bv = 3.402823466e38f; int bi = 0;
#pragma unroll
        for (int q = 0; q < 4; ++q) {
            int c = tid + q * 256;
            float s = fmaf(-2.f, dot[q], g_p2[c]);
            if (s < bv) { bv = s; bi = c; }
        }
        sv[tid] = bv; si[tid] = bi;
        __syncthreads();
        for (int o = 128; o > 0; o >>= 1) {
            if (tid < o) {
                float v2 = sv[tid + o]; int i2 = si[tid + o];
                if (v2 < sv[tid] || (v2 == sv[tid] && i2 < si[tid])) {
                    sv[tid] = v2; si[tid] = i2;
                }
            }
            __syncthreads();
        }
        if (tid == 0) {
            const float4* xr = reinterpret_cast<const float4*>(&X[(size_t)gr * DDIM]);
            float x2 = 0.f;
#pragma unroll 8
            for (int q = 0; q < 64; ++q) {
                float4 v = xr[q];
                x2 += v.x * v.x + v.y * v.y + v.z * v.z + v.w * v.w;
            }
            float d2 = fmaxf(x2 + sv[0], 0.f);
            out[gr]        = (float)si[0];
            out[NPTS + gr] = sqrtf(d2);
        }
        __syncthreads();
    }
}

// ---------------------------------------------------------------------------
// Host launcher
// ---------------------------------------------------------------------------
typedef CUresult (*PFN_tmapEncode)(
    CUtensorMap*, CUtensorMapDataType, cuuint32_t, void*,
    const cuuint64_t*, const cuuint64_t*, const cuuint32_t*, const cuuint32_t*,
    CUtensorMapInterleave, CUtensorMapSwizzle, CUtensorMapL2promotion,
    CUtensorMapFloatOOBfill);

static PFN_tmapEncode get_encode_fn() {
    static PFN_tmapEncode fn = nullptr;
    if (!fn) {
        void* p = nullptr;
        cudaDriverEntryPointQueryResult st;
        cudaGetDriverEntryPointByVersion("cuTensorMapEncodeTiled", &p, 12000,
                                         cudaEnableDefault, &st);
        fn = (PFN_tmapEncode)p;
    }
    return fn;
}

static void make_phi_map(CUtensorMap* map, void* ptr) {
    cuuint64_t dims[2]    = {DDIM, CDIM};           // inner = k, outer = rows
    cuuint64_t strides[1] = {DDIM * 2};             // 512 B per row
    cuuint32_t box[2]     = {64, 128};              // 128B x 128 rows (SW128)
    cuuint32_t es[2]      = {1, 1};
    get_encode_fn()(map, CU_TENSOR_MAP_DATA_TYPE_FLOAT16, 2, ptr,
                    dims, strides, box, es,
                    CU_TENSOR_MAP_INTERLEAVE_NONE, CU_TENSOR_MAP_SWIZZLE_128B,
                    CU_TENSOR_MAP_L2_PROMOTION_L2_128B,
                    CU_TENSOR_MAP_FLOAT_OOB_FILL_NONE);
}

extern "C" void kernel_launch(void* const* d_in, const int* in_sizes, int n_in,
                              void* d_out, int out_size) {
    const float* X = (const float*)d_in[0];
    const float* parents = (const float*)d_in[1];
    const float* epsilon = (const float*)d_in[2];
    float* out = (float*)d_out;

    void* cntPtr = nullptr;
    cudaGetSymbolAddress(&cntPtr, g_cnt);
    cudaMemsetAsync(cntPtr, 0, sizeof(int));

    void* phiH = nullptr;
    cudaGetSymbolAddress(&phiH, g_PhiH);
    CUtensorMap tmapH;
    make_phi_map(&tmapH, phiH);

    phi_kernel<<<dim3(DDIM / 32, CDIM / 64), 256>>>(parents, epsilon);
    p2_kernel<<<(CDIM * 32) / 256, 256>>>();

    static bool attrSet = false;   // idempotent attribute set (not a guard on work)
    if (!attrSet) {
        cudaFuncSetAttribute(dist_kernel, cudaFuncAttributeMaxDynamicSharedMemorySize,
                             SMEM_TOTAL);
        attrSet = true;
    }
    dist_kernel<<<(NPTS + 127) / 128, 256, SMEM_TOTAL>>>(X, out, tmapH);
    refine_kernel<<<1024, 256>>>(X, out);
}

// round 9
// speedup vs baseline: 3.7245x; 1.1756x over previous
#include <cuda_runtime.h>
#include <cuda.h>
#include <cuda_fp16.h>
#include <math.h>

#define NPTS 100000
#define CDIM 1024
#define DDIM 256
#define THRESH 8.0f

// Scratch (no allocations allowed)
__device__ __align__(16) float g_Phi[CDIM * DDIM];
__device__ __align__(16) __half g_PhiH[CDIM * DDIM];
__device__ float g_p2[CDIM];
__device__ int g_cnt;
__device__ int g_list[NPTS];

// ---------------------------------------------------------------------------
// PTX helpers (sm_100-safe: mma.sync + TMA + mbarrier only)
// ---------------------------------------------------------------------------
static __device__ __forceinline__ unsigned smem_u32(const void* p) {
    return (unsigned)__cvta_generic_to_shared(p);
}

#define SWZ128(off) ((off) ^ (((off) >> 3) & 0x70))

#define LDSM4(r0, r1, r2, r3, addr)                                            \
    asm volatile("ldmatrix.sync.aligned.m8n8.x4.shared.b16 {%0,%1,%2,%3}, [%4];" \
                 : "=r"(r0), "=r"(r1), "=r"(r2), "=r"(r3) : "r"(addr))

#define MMA16816F16(c, a, b)                                                   \
    asm volatile("mma.sync.aligned.m16n8k16.row.col.f32.f16.f16.f32 "          \
                 "{%0,%1,%2,%3}, {%4,%5,%6,%7}, {%8,%9}, {%0,%1,%2,%3};"       \
                 : "+f"((c)[0]), "+f"((c)[1]), "+f"((c)[2]), "+f"((c)[3])      \
                 : "r"((a)[0]), "r"((a)[1]), "r"((a)[2]), "r"((a)[3]),         \
                   "r"((b)[0]), "r"((b)[1]))

#define MBARRIER_INIT(mbar, cnt) \
    asm volatile("mbarrier.init.shared.b64 [%0], %1;" \
                 :: "r"((unsigned)(mbar)), "r"((unsigned)(cnt)) : "memory")
#define MBARRIER_EXPECT_TX(mbar, b) \
    asm volatile("mbarrier.arrive.expect_tx.shared.b64 _, [%0], %1;" \
                 :: "r"((unsigned)(mbar)), "r"((unsigned)(b)) : "memory")

static __device__ __forceinline__ void mbar_wait(unsigned mbar, unsigned parity) {
    asm volatile(
        "{\n\t"
        ".reg .pred P;\n\t"
        "W_%=:\n\t"
        "mbarrier.try_wait.parity.acquire.cta.shared::cta.b64 P, [%0], %1, 0x989680;\n\t"
        "@P bra D_%=;\n\t"
        "bra W_%=;\n\t"
        "D_%=:\n\t"
        "}"
        :: "r"(mbar), "r"(parity) : "memory");
}

static __device__ __forceinline__ void tma2d(unsigned dst, const CUtensorMap* map,
                                             int x, int y, unsigned mbar) {
    asm volatile(
        "cp.async.bulk.tensor.2d.shared::cta.global.tile.mbarrier::complete_tx::bytes "
        "[%0], [%1, {%2, %3}], [%4];"
        :: "r"(dst), "l"(map), "r"(x), "r"(y), "r"(mbar) : "memory");
}

// ---------------------------------------------------------------------------
// Kernel 1: Phi = parents @ epsilon. Sequential k 0..1023 per element (exact,
// matches reference ordering — DO NOT reassociate; one flip fails the test).
// ---------------------------------------------------------------------------
__global__ __launch_bounds__(256) void phi_kernel(const float* __restrict__ A,
                                                  const float* __restrict__ B) {
    __shared__ __align__(16) float As[16][64];
    __shared__ __align__(16) float Bs[16][36];
    const int tid = threadIdx.x;
    const int tx = tid & 15, ty = tid >> 4;
    const int m0 = blockIdx.y * 64;
    const int n0 = blockIdx.x * 32;
    float acc[4][2] = {};

    for (int k0 = 0; k0 < CDIM; k0 += 16) {
        __syncthreads();
        {
            int row = tid >> 2, c4 = tid & 3;
            float4 v = *reinterpret_cast<const float4*>(&A[(m0 + row) * CDIM + k0 + c4 * 4]);
            As[c4 * 4 + 0][row] = v.x;
            As[c4 * 4 + 1][row] = v.y;
            As[c4 * 4 + 2][row] = v.z;
            As[c4 * 4 + 3][row] = v.w;
        }
        if (tid < 128) {
            int row = tid >> 3, c8 = tid & 7;
            float4 v = *reinterpret_cast<const float4*>(&B[(k0 + row) * DDIM + n0 + c8 * 4]);
            Bs[row][c8 * 4 + 0] = v.x;
            Bs[row][c8 * 4 + 1] = v.y;
            Bs[row][c8 * 4 + 2] = v.z;
            Bs[row][c8 * 4 + 3] = v.w;
        }
        __syncthreads();
#pragma unroll
        for (int k = 0; k < 16; ++k) {
            float4 ra = *reinterpret_cast<const float4*>(&As[k][ty * 4]);
            float a[4] = {ra.x, ra.y, ra.z, ra.w};
            float b0 = Bs[k][tx * 2];
            float b1 = Bs[k][tx * 2 + 1];
#pragma unroll
            for (int i = 0; i < 4; ++i) {
                acc[i][0] = fmaf(a[i], b0, acc[i][0]);
                acc[i][1] = fmaf(a[i], b1, acc[i][1]);
            }
        }
    }
#pragma unroll
    for (int i = 0; i < 4; ++i) {
        float2 v = make_float2(acc[i][0], acc[i][1]);
        *reinterpret_cast<float2*>(&g_Phi[(m0 + ty * 4 + i) * DDIM + n0 + tx * 2]) = v;
    }
}

// ---------------------------------------------------------------------------
// Kernel 2: p2[c] = ||Phi_c||^2 (fp32) + fp16 copy of Phi.
// ---------------------------------------------------------------------------
__global__ __launch_bounds__(256) void p2_kernel() {
    int w = (blockIdx.x * blockDim.x + threadIdx.x) >> 5;
    int lane = threadIdx.x & 31;
    if (w >= CDIM) return;
    const float4* r = reinterpret_cast<const float4*>(&g_Phi[w * DDIM]);
    float4 a = r[lane];
    float4 b = r[lane + 32];
    __half* dh = &g_PhiH[w * DDIM];
    {
        __half2 h0 = __floats2half2_rn(a.x, a.y);
        __half2 h1 = __floats2half2_rn(a.z, a.w);
        *reinterpret_cast<__half2*>(&dh[lane * 4])     = h0;
        *reinterpret_cast<__half2*>(&dh[lane * 4 + 2]) = h1;
        __half2 h2 = __floats2half2_rn(b.x, b.y);
        __half2 h3 = __floats2half2_rn(b.z, b.w);
        *reinterpret_cast<__half2*>(&dh[128 + lane * 4])     = h2;
        *reinterpret_cast<__half2*>(&dh[128 + lane * 4 + 2]) = h3;
    }
    float s = a.x * a.x + a.y * a.y + a.z * a.z + a.w * a.w
            + b.x * b.x + b.y * b.y + b.z * b.z + b.w * b.w;
#pragma unroll
    for (int o = 16; o > 0; o >>= 1)
        s += __shfl_xor_sync(0xFFFFFFFFu, s, o);
    if (lane == 0) g_p2[w] = s;
}

// ---------------------------------------------------------------------------
// Kernel 3: single-pass fp16 mma.sync dots + argmin; Phi via TMA (SW128).
// Identical to the R8 kernel that passed at 465 us.
// ---------------------------------------------------------------------------
#define XS_STRIDE 264
#define XS_BYTES  (128 * XS_STRIDE * 2)          // 67584
#define X_OFF     1024
#define STG_OFF   (X_OFF + XS_BYTES)             // 68608 (1024-aligned)
#define P2_OFF    (STG_OFF + 2 * 16384)          // 101376
#define SMEM_TOTAL (P2_OFF + 4096)               // 105472

__global__ __launch_bounds__(256, 2)
void dist_kernel(const float* __restrict__ X, float* __restrict__ out,
                 const __grid_constant__ CUtensorMap tmapH) {
    extern __shared__ __align__(1024) char smem[];
    const unsigned SB = smem_u32(smem);
    __half* Xh = reinterpret_cast<__half*>(smem + X_OFF);
    float* p2s = reinterpret_cast<float*>(smem + P2_OFF);
    float* red_v = reinterpret_cast<float*>(smem + STG_OFF);
    int*   red_i = reinterpret_cast<int*>(smem + STG_OFF + 8192);
    float* red_s = reinterpret_cast<float*>(smem + STG_OFF + 16384);

    const int tid = threadIdx.x;
    const int lane = tid & 31, wid = tid >> 5;
    const int wm = wid >> 2, wn = wid & 3;
    const int mBase = wm * 64, nBase = wn * 32;
    const int rowBase = blockIdx.x * 128;

    if (tid == 0) {
        MBARRIER_INIT(SB + 0, 1);     // full[0]
        MBARRIER_INIT(SB + 8, 1);     // full[1]
    }

    for (int i = tid; i < 128 * 64; i += 256) {
        int r = i >> 6, q = i & 63;
        int gr = rowBase + r;
        float4 v = make_float4(0.f, 0.f, 0.f, 0.f);
        if (gr < NPTS)
            v = *reinterpret_cast<const float4*>(&X[(size_t)gr * DDIM + q * 4]);
        *reinterpret_cast<__half2*>(&Xh[r * XS_STRIDE + q * 4]) =
            __floats2half2_rn(v.x, v.y);
        *reinterpret_cast<__half2*>(&Xh[r * XS_STRIDE + q * 4 + 2]) =
            __floats2half2_rn(v.z, v.w);
    }
    for (int i = tid; i < CDIM; i += 256) p2s[i] = g_p2[i];
    __syncthreads();

    if (tid == 0) {
#pragma unroll
        for (int g = 0; g < 2; ++g) {
            unsigned mb = SB + (unsigned)g * 8;
            unsigned dst = SB + STG_OFF + (unsigned)g * 16384;
            MBARRIER_EXPECT_TX(mb, 16384);
            tma2d(dst, &tmapH, (g & 3) * 64, (g >> 2) * 128, mb);
        }
    }

    const int arow = lane & 15;
    const int ahalf = lane >> 4;
    const int brow = (lane & 7) | ((lane >> 1) & 8);
    const int bhalf = (lane >> 3) & 1;

    const unsigned XhB = smem_u32(Xh);
    const unsigned aOff = (unsigned)(((mBase + arow) * XS_STRIDE + ahalf * 8) * 2);

    float bestv[8], secondv[8];
    int   besti[8];
#pragma unroll
    for (int i = 0; i < 8; ++i) {
        bestv[i] = 3.402823466e38f; secondv[i] = 3.402823466e38f; besti[i] = 0;
    }

    float acc[4][4][4];
#pragma unroll
    for (int mt = 0; mt < 4; ++mt)
#pragma unroll
        for (int nt = 0; nt < 4; ++nt)
#pragma unroll
            for (int e = 0; e < 4; ++e) acc[mt][nt][e] = 0.f;

    for (int g = 0; g < 32; ++g) {                   // g = ct*4 + kc
        const int s = g & 1;
        const int kc = g & 3;
        mbar_wait(SB + (unsigned)s * 8, (unsigned)((g >> 1) & 1));
        const unsigned stH = SB + STG_OFF + (unsigned)s * 16384;
#pragma unroll
        for (int ks = 0; ks < 4; ++ks) {
            unsigned ah[4][4];
#pragma unroll
            for (int mt = 0; mt < 4; ++mt) {
                unsigned o = aOff + (unsigned)((mt * 16 * XS_STRIDE + kc * 64 + ks * 16) * 2);
                LDSM4(ah[mt][0], ah[mt][1], ah[mt][2], ah[mt][3], XhB + o);
            }
            unsigned bh[4][2];
#pragma unroll
            for (int nt2 = 0; nt2 < 2; ++nt2) {
                unsigned off = (unsigned)((nBase + nt2 * 16 + brow) * 128 +
                                          ks * 32 + bhalf * 16);
                off = SWZ128(off);
                LDSM4(bh[nt2 * 2][0], bh[nt2 * 2][1],
                      bh[nt2 * 2 + 1][0], bh[nt2 * 2 + 1][1], stH + off);
            }
#pragma unroll
            for (int mt = 0; mt < 4; ++mt)
#pragma unroll
                for (int nt = 0; nt < 4; ++nt)
                    MMA16816F16(acc[mt][nt], ah[mt], bh[nt]);
        }
        __syncthreads();
        if (tid == 0 && g + 2 < 32) {
            int g2 = g + 2;
            unsigned mb = SB + (unsigned)s * 8;
            unsigned dst = SB + STG_OFF + (unsigned)s * 16384;
            MBARRIER_EXPECT_TX(mb, 16384);
            tma2d(dst, &tmapH, (g2 & 3) * 64, (g2 >> 2) * 128, mb);
        }
        if (kc == 3) {
            const int colBase = (g >> 2) * 128;
#pragma unroll
            for (int nt = 0; nt < 4; ++nt) {
                int c0 = colBase + nBase + nt * 8 + (lane & 3) * 2;
                float p2a = p2s[c0];
                float p2b = p2s[c0 + 1];
#pragma unroll
                for (int mt = 0; mt < 4; ++mt) {
                    float sc[4];
                    sc[0] = fmaf(-2.f, acc[mt][nt][0], p2a);
                    sc[1] = fmaf(-2.f, acc[mt][nt][1], p2b);
                    sc[2] = fmaf(-2.f, acc[mt][nt][2], p2a);
                    sc[3] = fmaf(-2.f, acc[mt][nt][3], p2b);
#pragma unroll
                    for (int e = 0; e < 4; ++e) {
                        int slot = mt * 2 + (e >> 1);
                        int c = c0 + (e & 1);
                        if (sc[e] < bestv[slot]) {
                            secondv[slot] = bestv[slot];
                            bestv[slot] = sc[e]; besti[slot] = c;
                        } else if (sc[e] < secondv[slot]) {
                            secondv[slot] = sc[e];
                        }
                        acc[mt][nt][e] = 0.f;
                    }
                }
            }
        }
    }

    __syncthreads();
#pragma unroll
    for (int mt = 0; mt < 4; ++mt)
#pragma unroll
        for (int h = 0; h < 2; ++h) {
            int r = mBase + mt * 16 + (lane >> 2) + h * 8;
            red_v[r * 16 + wn * 4 + (lane & 3)] = bestv[mt * 2 + h];
            red_i[r * 16 + wn * 4 + (lane & 3)] = besti[mt * 2 + h];
            red_s[r * 16 + wn * 4 + (lane & 3)] = secondv[mt * 2 + h];
        }
    __syncthreads();

    if (tid < 128) {
        int gr = rowBase + tid;
        if (gr < NPTS) {
            float bv = red_v[tid * 16];
            int   bi = red_i[tid * 16];
            float sv = red_s[tid * 16];
#pragma unroll
            for (int t = 1; t < 16; ++t) {
                float v  = red_v[tid * 16 + t];
                int   ii = red_i[tid * 16 + t];
                float s2 = red_s[tid * 16 + t];
                if (v < bv || (v == bv && ii < bi)) {
                    sv = fminf(s2, bv);
                    bv = v; bi = ii;
                } else {
                    sv = fminf(sv, v);
                }
            }
            if (sv - bv < THRESH) {            // near-tie -> exact refinement
                int w = atomicAdd(&g_cnt, 1);
                g_list[w] = gr;
            }
            const float4* xr = reinterpret_cast<const float4*>(&X[(size_t)gr * DDIM]);
            float x2 = 0.f;
#pragma unroll 8
            for (int t = 0; t < 64; ++t) {
                float4 v = xr[t];
                x2 += v.x * v.x + v.y * v.y + v.z * v.z + v.w * v.w;
            }
            float d2 = fmaxf(x2 + bv, 0.f);
            out[gr]        = (float)bi;
            out[NPTS + gr] = sqrtf(d2);
        }
    }
}

// ---------------------------------------------------------------------------
// Kernel 4: exact fp32 refinement, coalesced. One block per flagged point.
// Warp w owns centroids [128w, 128w+128), 4 in flight; lane holds x[8l..8l+7];
// per centroid: 2 coalesced LDG.128/lane + 8 FMA + shuffle reduce.
// ---------------------------------------------------------------------------
__global__ __launch_bounds__(256) void refine_kernel(const float* __restrict__ X,
                                                     float* __restrict__ out) {
    __shared__ __align__(16) float xsh[DDIM];
    __shared__ float wv[8];
    __shared__ int   wi[8];
    const int tid = threadIdx.x;
    const int lane = tid & 31, wid = tid >> 5;
    const int nwork = g_cnt;

    for (int w = blockIdx.x; w < nwork; w += gridDim.x) {
        const int gr = g_list[w];
        __syncthreads();                       // protect xsh/wv reuse
        if (tid < 64)
            reinterpret_cast<float4*>(xsh)[tid] =
                reinterpret_cast<const float4*>(&X[(size_t)gr * DDIM])[tid];
        __syncthreads();

        float xf[8];
#pragma unroll
        for (int i = 0; i < 8; ++i) xf[i] = xsh[lane * 8 + i];

        float bv = 3.402823466e38f; int bi = 0;
        for (int c0 = wid * 128; c0 < wid * 128 + 128; c0 += 4) {
            float d[4];
#pragma unroll
            for (int q = 0; q < 4; ++q) {
                const float4* pr = reinterpret_cast<const float4*>(
                    &g_Phi[(size_t)(c0 + q) * DDIM]);
                float4 p0 = pr[lane * 2];
                float4 p1 = pr[lane * 2 + 1];
                float s;
                s = xf[0] * p0.x;
                s = fmaf(xf[1], p0.y, s);
                s = fmaf(xf[2], p0.z, s);
                s = fmaf(xf[3], p0.w, s);
                s = fmaf(xf[4], p1.x, s);
                s = fmaf(xf[5], p1.y, s);
                s = fmaf(xf[6], p1.z, s);
                s = fmaf(xf[7], p1.w, s);
                d[q] = s;
            }
#pragma unroll
            for (int q = 0; q < 4; ++q) {
#pragma unroll
                for (int o = 16; o > 0; o >>= 1)
                    d[q] += __shfl_xor_sync(0xFFFFFFFFu, d[q], o);
                float s = fmaf(-2.f, d[q], g_p2[c0 + q]);
                if (s < bv) { bv = s; bi = c0 + q; }   // ascending c: first-min
            }
        }
        if (lane == 0) { wv[wid] = bv; wi[wid] = bi; }
        __syncthreads();
        if (tid == 0) {
            float b = wv[0]; int ii = wi[0];
#pragma unroll
            for (int t = 1; t < 8; ++t)
                if (wv[t] < b || (wv[t] == b && wi[t] < ii)) { b = wv[t]; ii = wi[t]; }
            float x2 = 0.f;
            for (int t = 0; t < DDIM; ++t) x2 = fmaf(xsh[t], xsh[t], x2);
            out[gr]        = (float)ii;
            out[NPTS + gr] = sqrtf(fmaxf(x2 + b, 0.f));
        }
    }
}

// ---------------------------------------------------------------------------
// Host launcher
// ---------------------------------------------------------------------------
typedef CUresult (*PFN_tmapEncode)(
    CUtensorMap*, CUtensorMapDataType, cuuint32_t, void*,
    const cuuint64_t*, const cuuint64_t*, const cuuint32_t*, const cuuint32_t*,
    CUtensorMapInterleave, CUtensorMapSwizzle, CUtensorMapL2promotion,
    CUtensorMapFloatOOBfill);

static PFN_tmapEncode get_encode_fn() {
    static PFN_tmapEncode fn = nullptr;
    if (!fn) {
        void* p = nullptr;
        cudaDriverEntryPointQueryResult st;
        cudaGetDriverEntryPointByVersion("cuTensorMapEncodeTiled", &p, 12000,
                                         cudaEnableDefault, &st);
        fn = (PFN_tmapEncode)p;
    }
    return fn;
}

static void make_phi_map(CUtensorMap* map, void* ptr) {
    cuuint64_t dims[2]    = {DDIM, CDIM};
    cuuint64_t strides[1] = {DDIM * 2};
    cuuint32_t box[2]     = {64, 128};
    cuuint32_t es[2]      = {1, 1};
    get_encode_fn()(map, CU_TENSOR_MAP_DATA_TYPE_FLOAT16, 2, ptr,
                    dims, strides, box, es,
                    CU_TENSOR_MAP_INTERLEAVE_NONE, CU_TENSOR_MAP_SWIZZLE_128B,
                    CU_TENSOR_MAP_L2_PROMOTION_L2_128B,
                    CU_TENSOR_MAP_FLOAT_OOB_FILL_NONE);
}

extern "C" void kernel_launch(void* const* d_in, const int* in_sizes, int n_in,
                              void* d_out, int out_size) {
    const float* X = (const float*)d_in[0];
    const float* parents = (const float*)d_in[1];
    const float* epsilon = (const float*)d_in[2];
    float* out = (float*)d_out;

    void* cntPtr = nullptr;
    cudaGetSymbolAddress(&cntPtr, g_cnt);
    cudaMemsetAsync(cntPtr, 0, sizeof(int));

    void* phiH = nullptr;
    cudaGetSymbolAddress(&phiH, g_PhiH);
    CUtensorMap tmapH;
    make_phi_map(&tmapH, phiH);

    phi_kernel<<<dim3(DDIM / 32, CDIM / 64), 256>>>(parents, epsilon);
    p2_kernel<<<(CDIM * 32) / 256, 256>>>();

    static bool attrSet = false;   // idempotent attribute set (not a guard on work)
    if (!attrSet) {
        cudaFuncSetAttribute(dist_kernel, cudaFuncAttributeMaxDynamicSharedMemorySize,
                             SMEM_TOTAL);
        attrSet = true;
    }
    dist_kernel<<<(NPTS + 127) / 128, 256, SMEM_TOTAL>>>(X, out, tmapH);
    refine_kernel<<<256, 256>>>(X, out);
}

// round 11
// speedup vs baseline: 4.3636x; 1.1716x over previous
#include <cuda_runtime.h>
#include <cuda.h>
#include <cuda_fp16.h>
#include <math.h>

#define NPTS 100000
#define CDIM 1024
#define DDIM 256
#define THRESH 8.0f

// Scratch (no allocations allowed)
__device__ __align__(16) float g_Phi[CDIM * DDIM];
__device__ __align__(16) __half g_PhiH[CDIM * DDIM];
__device__ float g_p2[CDIM];
__device__ int g_cnt;
__device__ int g_list[NPTS];
__device__ unsigned long long g_best[NPTS];

// ---------------------------------------------------------------------------
// PTX helpers (sm_100-safe: mma.sync + TMA + mbarrier only)
// ---------------------------------------------------------------------------
static __device__ __forceinline__ unsigned smem_u32(const void* p) {
    return (unsigned)__cvta_generic_to_shared(p);
}

#define SWZ128(off) ((off) ^ (((off) >> 3) & 0x70))

#define LDSM4(r0, r1, r2, r3, addr)                                            \
    asm volatile("ldmatrix.sync.aligned.m8n8.x4.shared.b16 {%0,%1,%2,%3}, [%4];" \
                 : "=r"(r0), "=r"(r1), "=r"(r2), "=r"(r3) : "r"(addr))

#define MMA16816F16(c, a, b)                                                   \
    asm volatile("mma.sync.aligned.m16n8k16.row.col.f32.f16.f16.f32 "          \
                 "{%0,%1,%2,%3}, {%4,%5,%6,%7}, {%8,%9}, {%0,%1,%2,%3};"       \
                 : "+f"((c)[0]), "+f"((c)[1]), "+f"((c)[2]), "+f"((c)[3])      \
                 : "r"((a)[0]), "r"((a)[1]), "r"((a)[2]), "r"((a)[3]),         \
                   "r"((b)[0]), "r"((b)[1]))

#define MBARRIER_INIT(mbar, cnt) \
    asm volatile("mbarrier.init.shared.b64 [%0], %1;" \
                 :: "r"((unsigned)(mbar)), "r"((unsigned)(cnt)) : "memory")
#define MBARRIER_EXPECT_TX(mbar, b) \
    asm volatile("mbarrier.arrive.expect_tx.shared.b64 _, [%0], %1;" \
                 :: "r"((unsigned)(mbar)), "r"((unsigned)(b)) : "memory")

static __device__ __forceinline__ void mbar_wait(unsigned mbar, unsigned parity) {
    asm volatile(
        "{\n\t"
        ".reg .pred P;\n\t"
        "W_%=:\n\t"
        "mbarrier.try_wait.parity.acquire.cta.shared::cta.b64 P, [%0], %1, 0x989680;\n\t"
        "@P bra D_%=;\n\t"
        "bra W_%=;\n\t"
        "D_%=:\n\t"
        "}"
        :: "r"(mbar), "r"(parity) : "memory");
}

static __device__ __forceinline__ void tma2d(unsigned dst, const CUtensorMap* map,
                                             int x, int y, unsigned mbar) {
    asm volatile(
        "cp.async.bulk.tensor.2d.shared::cta.global.tile.mbarrier::complete_tx::bytes "
        "[%0], [%1, {%2, %3}], [%4];"
        :: "r"(dst), "l"(map), "r"(x), "r"(y), "r"(mbar) : "memory");
}

// Monotonic float <-> ordered-uint encoding (min of key = min score, then idx)
static __device__ __forceinline__ unsigned f2ord(float f) {
    unsigned u = __float_as_uint(f);
    return (u & 0x80000000u) ? ~u : (u | 0x80000000u);
}
static __device__ __forceinline__ float ord2f(unsigned o) {
    unsigned u = (o & 0x80000000u) ? (o ^ 0x80000000u) : ~o;
    return __uint_as_float(u);
}

// ---------------------------------------------------------------------------
// Kernel 1: Phi = parents @ epsilon. Sequential k 0..1023 per element (exact,
// matches reference ordering — DO NOT reassociate; one flip fails the test).
// ---------------------------------------------------------------------------
__global__ __launch_bounds__(256) void phi_kernel(const float* __restrict__ A,
                                                  const float* __restrict__ B) {
    __shared__ __align__(16) float As[16][64];
    __shared__ __align__(16) float Bs[16][36];
    const int tid = threadIdx.x;
    const int tx = tid & 15, ty = tid >> 4;
    const int m0 = blockIdx.y * 64;
    const int n0 = blockIdx.x * 32;
    float acc[4][2] = {};

    for (int k0 = 0; k0 < CDIM; k0 += 16) {
        __syncthreads();
        {
            int row = tid >> 2, c4 = tid & 3;
            float4 v = *reinterpret_cast<const float4*>(&A[(m0 + row) * CDIM + k0 + c4 * 4]);
            As[c4 * 4 + 0][row] = v.x;
            As[c4 * 4 + 1][row] = v.y;
            As[c4 * 4 + 2][row] = v.z;
            As[c4 * 4 + 3][row] = v.w;
        }
        if (tid < 128) {
            int row = tid >> 3, c8 = tid & 7;
            float4 v = *reinterpret_cast<const float4*>(&B[(k0 + row) * DDIM + n0 + c8 * 4]);
            Bs[row][c8 * 4 + 0] = v.x;
            Bs[row][c8 * 4 + 1] = v.y;
            Bs[row][c8 * 4 + 2] = v.z;
            Bs[row][c8 * 4 + 3] = v.w;
        }
        __syncthreads();
#pragma unroll
        for (int k = 0; k < 16; ++k) {
            float4 ra = *reinterpret_cast<const float4*>(&As[k][ty * 4]);
            float a[4] = {ra.x, ra.y, ra.z, ra.w};
            float b0 = Bs[k][tx * 2];
            float b1 = Bs[k][tx * 2 + 1];
#pragma unroll
            for (int i = 0; i < 4; ++i) {
                acc[i][0] = fmaf(a[i], b0, acc[i][0]);
                acc[i][1] = fmaf(a[i], b1, acc[i][1]);
            }
        }
    }
#pragma unroll
    for (int i = 0; i < 4; ++i) {
        float2 v = make_float2(acc[i][0], acc[i][1]);
        *reinterpret_cast<float2*>(&g_Phi[(m0 + ty * 4 + i) * DDIM + n0 + tx * 2]) = v;
    }
}

// ---------------------------------------------------------------------------
// Kernel 2: p2[c] = ||Phi_c||^2 (fp32) + fp16 copy of Phi.
// ---------------------------------------------------------------------------
__global__ __launch_bounds__(256) void p2_kernel() {
    int w = (blockIdx.x * blockDim.x + threadIdx.x) >> 5;
    int lane = threadIdx.x & 31;
    if (w >= CDIM) return;
    const float4* r = reinterpret_cast<const float4*>(&g_Phi[w * DDIM]);
    float4 a = r[lane];
    float4 b = r[lane + 32];
    __half* dh = &g_PhiH[w * DDIM];
    {
        __half2 h0 = __floats2half2_rn(a.x, a.y);
        __half2 h1 = __floats2half2_rn(a.z, a.w);
        *reinterpret_cast<__half2*>(&dh[lane * 4])     = h0;
        *reinterpret_cast<__half2*>(&dh[lane * 4 + 2]) = h1;
        __half2 h2 = __floats2half2_rn(b.x, b.y);
        __half2 h3 = __floats2half2_rn(b.z, b.w);
        *reinterpret_cast<__half2*>(&dh[128 + lane * 4])     = h2;
        *reinterpret_cast<__half2*>(&dh[128 + lane * 4 + 2]) = h3;
    }
    float s = a.x * a.x + a.y * a.y + a.z * a.z + a.w * a.w
            + b.x * b.x + b.y * b.y + b.z * b.z + b.w * b.w;
#pragma unroll
    for (int o = 16; o > 0; o >>= 1)
        s += __shfl_xor_sync(0xFFFFFFFFu, s, o);
    if (lane == 0) g_p2[w] = s;
}

// ---------------------------------------------------------------------------
// Kernel 3: single-pass fp16 mma.sync dots + argmin; Phi via TMA (SW128).
// Identical to the R8/R9 kernel that passed, plus g_best init at flag time.
// ---------------------------------------------------------------------------
#define XS_STRIDE 264
#define XS_BYTES  (128 * XS_STRIDE * 2)          // 67584
#define X_OFF     1024
#define STG_OFF   (X_OFF + XS_BYTES)             // 68608 (1024-aligned)
#define P2_OFF    (STG_OFF + 2 * 16384)          // 101376
#define SMEM_TOTAL (P2_OFF + 4096)               // 105472

__global__ __launch_bounds__(256, 2)
void dist_kernel(const float* __restrict__ X, float* __restrict__ out,
                 const __grid_constant__ CUtensorMap tmapH) {
    extern __shared__ __align__(1024) char smem[];
    const unsigned SB = smem_u32(smem);
    __half* Xh = reinterpret_cast<__half*>(smem + X_OFF);
    float* p2s = reinterpret_cast<float*>(smem + P2_OFF);
    float* red_v = reinterpret_cast<float*>(smem + STG_OFF);
    int*   red_i = reinterpret_cast<int*>(smem + STG_OFF + 8192);
    float* red_s = reinterpret_cast<float*>(smem + STG_OFF + 16384);

    const int tid = threadIdx.x;
    const int lane = tid & 31, wid = tid >> 5;
    const int wm = wid >> 2, wn = wid & 3;
    const int mBase = wm * 64, nBase = wn * 32;
    const int rowBase = blockIdx.x * 128;

    if (tid == 0) {
        MBARRIER_INIT(SB + 0, 1);     // full[0]
        MBARRIER_INIT(SB + 8, 1);     // full[1]
    }

    for (int i = tid; i < 128 * 64; i += 256) {
        int r = i >> 6, q = i & 63;
        int gr = rowBase + r;
        float4 v = make_float4(0.f, 0.f, 0.f, 0.f);
        if (gr < NPTS)
            v = *reinterpret_cast<const float4*>(&X[(size_t)gr * DDIM + q * 4]);
        *reinterpret_cast<__half2*>(&Xh[r * XS_STRIDE + q * 4]) =
            __floats2half2_rn(v.x, v.y);
        *reinterpret_cast<__half2*>(&Xh[r * XS_STRIDE + q * 4 + 2]) =
            __floats2half2_rn(v.z, v.w);
    }
    for (int i = tid; i < CDIM; i += 256) p2s[i] = g_p2[i];
    __syncthreads();

    if (tid == 0) {
#pragma unroll
        for (int g = 0; g < 2; ++g) {
            unsigned mb = SB + (unsigned)g * 8;
            unsigned dst = SB + STG_OFF + (unsigned)g * 16384;
            MBARRIER_EXPECT_TX(mb, 16384);
            tma2d(dst, &tmapH, (g & 3) * 64, (g >> 2) * 128, mb);
        }
    }

    const int arow = lane & 15;
    const int ahalf = lane >> 4;
    const int brow = (lane & 7) | ((lane >> 1) & 8);
    const int bhalf = (lane >> 3) & 1;

    const unsigned XhB = smem_u32(Xh);
    const unsigned aOff = (unsigned)(((mBase + arow) * XS_STRIDE + ahalf * 8) * 2);

    float bestv[8], secondv[8];
    int   besti[8];
#pragma unroll
    for (int i = 0; i < 8; ++i) {
        bestv[i] = 3.402823466e38f; secondv[i] = 3.402823466e38f; besti[i] = 0;
    }

    float acc[4][4][4];
#pragma unroll
    for (int mt = 0; mt < 4; ++mt)
#pragma unroll
        for (int nt = 0; nt < 4; ++nt)
#pragma unroll
            for (int e = 0; e < 4; ++e) acc[mt][nt][e] = 0.f;

    for (int g = 0; g < 32; ++g) {                   // g = ct*4 + kc
        const int s = g & 1;
        const int kc = g & 3;
        mbar_wait(SB + (unsigned)s * 8, (unsigned)((g >> 1) & 1));
        const unsigned stH = SB + STG_OFF + (unsigned)s * 16384;
#pragma unroll
        for (int ks = 0; ks < 4; ++ks) {
            unsigned ah[4][4];
#pragma unroll
            for (int mt = 0; mt < 4; ++mt) {
                unsigned o = aOff + (unsigned)((mt * 16 * XS_STRIDE + kc * 64 + ks * 16) * 2);
                LDSM4(ah[mt][0], ah[mt][1], ah[mt][2], ah[mt][3], XhB + o);
            }
            unsigned bh[4][2];
#pragma unroll
            for (int nt2 = 0; nt2 < 2; ++nt2) {
                unsigned off = (unsigned)((nBase + nt2 * 16 + brow) * 128 +
                                          ks * 32 + bhalf * 16);
                off = SWZ128(off);
                LDSM4(bh[nt2 * 2][0], bh[nt2 * 2][1],
                      bh[nt2 * 2 + 1][0], bh[nt2 * 2 + 1][1], stH + off);
            }
#pragma unroll
            for (int mt = 0; mt < 4; ++mt)
#pragma unroll
                for (int nt = 0; nt < 4; ++nt)
                    MMA16816F16(acc[mt][nt], ah[mt], bh[nt]);
        }
        __syncthreads();
        if (tid == 0 && g + 2 < 32) {
            int g2 = g + 2;
            unsigned mb = SB + (unsigned)s * 8;
            unsigned dst = SB + STG_OFF + (unsigned)s * 16384;
            MBARRIER_EXPECT_TX(mb, 16384);
            tma2d(dst, &tmapH, (g2 & 3) * 64, (g2 >> 2) * 128, mb);
        }
        if (kc == 3) {
            const int colBase = (g >> 2) * 128;
#pragma unroll
            for (int nt = 0; nt < 4; ++nt) {
                int c0 = colBase + nBase + nt * 8 + (lane & 3) * 2;
                float p2a = p2s[c0];
                float p2b = p2s[c0 + 1];
#pragma unroll
                for (int mt = 0; mt < 4; ++mt) {
                    float sc[4];
                    sc[0] = fmaf(-2.f, acc[mt][nt][0], p2a);
                    sc[1] = fmaf(-2.f, acc[mt][nt][1], p2b);
                    sc[2] = fmaf(-2.f, acc[mt][nt][2], p2a);
                    sc[3] = fmaf(-2.f, acc[mt][nt][3], p2b);
#pragma unroll
                    for (int e = 0; e < 4; ++e) {
                        int slot = mt * 2 + (e >> 1);
                        int c = c0 + (e & 1);
                        if (sc[e] < bestv[slot]) {
                            secondv[slot] = bestv[slot];
                            bestv[slot] = sc[e]; besti[slot] = c;
                        } else if (sc[e] < secondv[slot]) {
                            secondv[slot] = sc[e];
                        }
                        acc[mt][nt][e] = 0.f;
                    }
                }
            }
        }
    }

    __syncthreads();
#pragma unroll
    for (int mt = 0; mt < 4; ++mt)
#pragma unroll
        for (int h = 0; h < 2; ++h) {
            int r = mBase + mt * 16 + (lane >> 2) + h * 8;
            red_v[r * 16 + wn * 4 + (lane & 3)] = bestv[mt * 2 + h];
            red_i[r * 16 + wn * 4 + (lane & 3)] = besti[mt * 2 + h];
            red_s[r * 16 + wn * 4 + (lane & 3)] = secondv[mt * 2 + h];
        }
    __syncthreads();

    if (tid < 128) {
        int gr = rowBase + tid;
        if (gr < NPTS) {
            float bv = red_v[tid * 16];
            int   bi = red_i[tid * 16];
            float sv = red_s[tid * 16];
#pragma unroll
            for (int t = 1; t < 16; ++t) {
                float v  = red_v[tid * 16 + t];
                int   ii = red_i[tid * 16 + t];
                float s2 = red_s[tid * 16 + t];
                if (v < bv || (v == bv && ii < bi)) {
                    sv = fminf(s2, bv);
                    bv = v; bi = ii;
                } else {
                    sv = fminf(sv, v);
                }
            }
            if (sv - bv < THRESH) {            // near-tie -> exact refinement
                int w = atomicAdd(&g_cnt, 1);
                g_list[w] = gr;
                g_best[w] = 0xFFFFFFFFFFFFFFFFull;
            }
            const float4* xr = reinterpret_cast<const float4*>(&X[(size_t)gr * DDIM]);
            float x2 = 0.f;
#pragma unroll 8
            for (int t = 0; t < 64; ++t) {
                float4 v = xr[t];
                x2 += v.x * v.x + v.y * v.y + v.z * v.z + v.w * v.w;
            }
            float d2 = fmaxf(x2 + bv, 0.f);
            out[gr]        = (float)bi;
            out[NPTS + gr] = sqrtf(d2);
        }
    }
}

// ---------------------------------------------------------------------------
// Kernel 4a: exact fp32 refinement, parallel over (point x 128-centroid tile).
// Task = w*8 + ct. Warp handles 16 centroids (same inner loop as the passing
// R9 refine); block min -> one atomicMin(u64) into g_best[w].
// ---------------------------------------------------------------------------
__global__ __launch_bounds__(256) void refine_score(const float* __restrict__ X) {
    __shared__ __align__(16) float xsh[DDIM];
    __shared__ unsigned long long wmin[8];
    const int tid = threadIdx.x;
    const int lane = tid & 31, wid = tid >> 5;
    const int ntask = g_cnt * 8;

    for (int task = blockIdx.x; task < ntask; task += gridDim.x) {
        const int w = task >> 3;
        const int ctb = (task & 7) * 128;
        const int gr = g_list[w];
        __syncthreads();                       // protect xsh/wmin reuse
        if (tid < 64)
            reinterpret_cast<float4*>(xsh)[tid] =
                reinterpret_cast<const float4*>(&X[(size_t)gr * DDIM])[tid];
        __syncthreads();

        float xf[8];
#pragma unroll
        for (int i = 0; i < 8; ++i) xf[i] = xsh[lane * 8 + i];

        float bv = 3.402823466e38f; int bi = 0;
        const int cw = ctb + wid * 16;
        for (int c0 = cw; c0 < cw + 16; c0 += 4) {
            float d[4];
#pragma unroll
            for (int q = 0; q < 4; ++q) {
                const float4* pr = reinterpret_cast<const float4*>(
                    &g_Phi[(size_t)(c0 + q) * DDIM]);
                float4 p0 = pr[lane * 2];
                float4 p1 = pr[lane * 2 + 1];
                float s;
                s = xf[0] * p0.x;
                s = fmaf(xf[1], p0.y, s);
                s = fmaf(xf[2], p0.z, s);
                s = fmaf(xf[3], p0.w, s);
                s = fmaf(xf[4], p1.x, s);
                s = fmaf(xf[5], p1.y, s);
                s = fmaf(xf[6], p1.z, s);
                s = fmaf(xf[7], p1.w, s);
                d[q] = s;
            }
#pragma unroll
            for (int q = 0; q < 4; ++q) {
#pragma unroll
                for (int o = 16; o > 0; o >>= 1)
                    d[q] += __shfl_xor_sync(0xFFFFFFFFu, d[q], o);
                float s = fmaf(-2.f, d[q], g_p2[c0 + q]);
                if (s < bv) { bv = s; bi = c0 + q; }   // ascending c: first-min
            }
        }
        if (lane == 0)
            wmin[wid] = ((unsigned long long)f2ord(bv) << 32) | (unsigned)bi;
        __syncthreads();
        if (tid == 0) {
            unsigned long long m = wmin[0];
#pragma unroll
            for (int t = 1; t < 8; ++t) m = (wmin[t] < m) ? wmin[t] : m;
            atomicMin(&g_best[w], m);
        }
    }
}

// ---------------------------------------------------------------------------
// Kernel 4b: writeback — decode per-point key, compute x2, store outputs.
// ---------------------------------------------------------------------------
__global__ __launch_bounds__(256) void refine_write(const float* __restrict__ X,
                                                    float* __restrict__ out) {
    const int lane = threadIdx.x & 31;
    const int gw = (blockIdx.x * 256 + threadIdx.x) >> 5;
    const int nw = gridDim.x * 8;
    const int nwork = g_cnt;

    for (int w = gw; w < nwork; w += nw) {
        const int gr = g_list[w];
        unsigned long long key = g_best[w];
        int bi = (int)(unsigned)(key & 0xFFFFFFFFull);
        float bv = ord2f((unsigned)(key >> 32));
        const float4* xr = reinterpret_cast<const float4*>(&X[(size_t)gr * DDIM]);
        float4 a = xr[lane];
        float4 b = xr[lane + 32];
        float x2 = a.x * a.x + a.y * a.y + a.z * a.z + a.w * a.w
                 + b.x * b.x + b.y * b.y + b.z * b.z + b.w * b.w;
#pragma unroll
        for (int o = 16; o > 0; o >>= 1)
            x2 += __shfl_xor_sync(0xFFFFFFFFu, x2, o);
        if (lane == 0) {
            out[gr]        = (float)bi;
            out[NPTS + gr] = sqrtf(fmaxf(x2 + bv, 0.f));
        }
    }
}

// ---------------------------------------------------------------------------
// Host launcher
// ---------------------------------------------------------------------------
typedef CUresult (*PFN_tmapEncode)(
    CUtensorMap*, CUtensorMapDataType, cuuint32_t, void*,
    const cuuint64_t*, const cuuint64_t*, const cuuint32_t*, const cuuint32_t*,
    CUtensorMapInterleave, CUtensorMapSwizzle, CUtensorMapL2promotion,
    CUtensorMapFloatOOBfill);

static PFN_tmapEncode get_encode_fn() {
    static PFN_tmapEncode fn = nullptr;
    if (!fn) {
        void* p = nullptr;
        cudaDriverEntryPointQueryResult st;
        cudaGetDriverEntryPointByVersion("cuTensorMapEncodeTiled", &p, 12000,
                                         cudaEnableDefault, &st);
        fn = (PFN_tmapEncode)p;
    }
    return fn;
}

static void make_phi_map(CUtensorMap* map, void* ptr) {
    cuuint64_t dims[2]    = {DDIM, CDIM};
    cuuint64_t strides[1] = {DDIM * 2};
    cuuint32_t box[2]     = {64, 128};
    cuuint32_t es[2]      = {1, 1};
    get_encode_fn()(map, CU_TENSOR_MAP_DATA_TYPE_FLOAT16, 2, ptr,
                    dims, strides, box, es,
                    CU_TENSOR_MAP_INTERLEAVE_NONE, CU_TENSOR_MAP_SWIZZLE_128B,
                    CU_TENSOR_MAP_L2_PROMOTION_L2_128B,
                    CU_TENSOR_MAP_FLOAT_OOB_FILL_NONE);
}

extern "C" void kernel_launch(void* const* d_in, const int* in_sizes, int n_in,
                              void* d_out, int out_size) {
    const float* X = (const float*)d_in[0];
    const float* parents = (const float*)d_in[1];
    const float* epsilon = (const float*)d_in[2];
    float* out = (float*)d_out;

    void* cntPtr = nullptr;
    cudaGetSymbolAddress(&cntPtr, g_cnt);
    cudaMemsetAsync(cntPtr, 0, sizeof(int));

    void* phiH = nullptr;
    cudaGetSymbolAddress(&phiH, g_PhiH);
    CUtensorMap tmapH;
    make_phi_map(&tmapH, phiH);

    phi_kernel<<<dim3(DDIM / 32, CDIM / 64), 256>>>(parents, epsilon);
    p2_kernel<<<(CDIM * 32) / 256, 256>>>();

    static bool attrSet = false;   // idempotent attribute set (not a guard on work)
    if (!attrSet) {
        cudaFuncSetAttribute(dist_kernel, cudaFuncAttributeMaxDynamicSharedMemorySize,
                             SMEM_TOTAL);
        attrSet = true;
    }
    dist_kernel<<<(NPTS + 127) / 128, 256, SMEM_TOTAL>>>(X, out, tmapH);
    refine_score<<<1184, 256>>>(X);
    refine_write<<<64, 256>>>(X, out);
}

// round 12
// speedup vs baseline: 4.4582x; 1.0217x over previous
#include <cuda_runtime.h>
#include <cuda.h>
#include <cuda_fp16.h>
#include <math.h>

#define NPTS 100000
#define CDIM 1024
#define DDIM 256
#define THRESH 8.0f

// Scratch (no allocations allowed)
__device__ __align__(16) float g_Phi[CDIM * DDIM];
__device__ __align__(16) __half g_PhiH[CDIM * DDIM];
__device__ float g_p2[CDIM];
__device__ int g_cnt;
__device__ int g_list[NPTS];
__device__ unsigned long long g_best[NPTS];

// ---------------------------------------------------------------------------
// PTX helpers (sm_100-safe: mma.sync + TMA + mbarrier only)
// ---------------------------------------------------------------------------
static __device__ __forceinline__ unsigned smem_u32(const void* p) {
    return (unsigned)__cvta_generic_to_shared(p);
}

#define SWZ128(off) ((off) ^ (((off) >> 3) & 0x70))

#define LDSM4(r0, r1, r2, r3, addr)                                            \
    asm volatile("ldmatrix.sync.aligned.m8n8.x4.shared.b16 {%0,%1,%2,%3}, [%4];" \
                 : "=r"(r0), "=r"(r1), "=r"(r2), "=r"(r3) : "r"(addr))

#define MMA16816F16(c, a, b)                                                   \
    asm volatile("mma.sync.aligned.m16n8k16.row.col.f32.f16.f16.f32 "          \
                 "{%0,%1,%2,%3}, {%4,%5,%6,%7}, {%8,%9}, {%0,%1,%2,%3};"       \
                 : "+f"((c)[0]), "+f"((c)[1]), "+f"((c)[2]), "+f"((c)[3])      \
                 : "r"((a)[0]), "r"((a)[1]), "r"((a)[2]), "r"((a)[3]),         \
                   "r"((b)[0]), "r"((b)[1]))

#define MBARRIER_INIT(mbar, cnt) \
    asm volatile("mbarrier.init.shared.b64 [%0], %1;" \
                 :: "r"((unsigned)(mbar)), "r"((unsigned)(cnt)) : "memory")
#define MBARRIER_EXPECT_TX(mbar, b) \
    asm volatile("mbarrier.arrive.expect_tx.shared.b64 _, [%0], %1;" \
                 :: "r"((unsigned)(mbar)), "r"((unsigned)(b)) : "memory")

static __device__ __forceinline__ void mbar_wait(unsigned mbar, unsigned parity) {
    asm volatile(
        "{\n\t"
        ".reg .pred P;\n\t"
        "W_%=:\n\t"
        "mbarrier.try_wait.parity.acquire.cta.shared::cta.b64 P, [%0], %1, 0x989680;\n\t"
        "@P bra D_%=;\n\t"
        "bra W_%=;\n\t"
        "D_%=:\n\t"
        "}"
        :: "r"(mbar), "r"(parity) : "memory");
}

static __device__ __forceinline__ void tma2d(unsigned dst, const CUtensorMap* map,
                                             int x, int y, unsigned mbar) {
    asm volatile(
        "cp.async.bulk.tensor.2d.shared::cta.global.tile.mbarrier::complete_tx::bytes "
        "[%0], [%1, {%2, %3}], [%4];"
        :: "r"(dst), "l"(map), "r"(x), "r"(y), "r"(mbar) : "memory");
}

// Monotonic float <-> ordered-uint encoding (min of key = min score, then idx)
static __device__ __forceinline__ unsigned f2ord(float f) {
    unsigned u = __float_as_uint(f);
    return (u & 0x80000000u) ? ~u : (u | 0x80000000u);
}
static __device__ __forceinline__ float ord2f(unsigned o) {
    unsigned u = (o & 0x80000000u) ? (o ^ 0x80000000u) : ~o;
    return __uint_as_float(u);
}

// ---------------------------------------------------------------------------
// Kernel 1: Phi = parents @ epsilon. Sequential k 0..1023 per element (exact,
// matches reference ordering — DO NOT reassociate; one flip fails the test).
// 32x32 tiles -> 256 blocks for better chip fill; per-element arithmetic
// identical to the validated 64x32 version.
// ---------------------------------------------------------------------------
__global__ __launch_bounds__(256) void phi_kernel(const float* __restrict__ A,
                                                  const float* __restrict__ B) {
    __shared__ __align__(16) float As[16][34];
    __shared__ __align__(16) float Bs[16][36];
    const int tid = threadIdx.x;
    const int tx = tid & 15, ty = tid >> 4;
    const int m0 = blockIdx.y * 32;
    const int n0 = blockIdx.x * 32;
    float acc[2][2] = {};

    for (int k0 = 0; k0 < CDIM; k0 += 16) {
        __syncthreads();
        if (tid < 128) {   // A tile 32x16 -> As[k][m] (transposed)
            int row = tid >> 2, c4 = tid & 3;
            float4 v = *reinterpret_cast<const float4*>(&A[(m0 + row) * CDIM + k0 + c4 * 4]);
            As[c4 * 4 + 0][row] = v.x;
            As[c4 * 4 + 1][row] = v.y;
            As[c4 * 4 + 2][row] = v.z;
            As[c4 * 4 + 3][row] = v.w;
        } else {           // B tile 16x32
            int t = tid - 128;
            int row = t >> 3, c8 = t & 7;
            float4 v = *reinterpret_cast<const float4*>(&B[(k0 + row) * DDIM + n0 + c8 * 4]);
            Bs[row][c8 * 4 + 0] = v.x;
            Bs[row][c8 * 4 + 1] = v.y;
            Bs[row][c8 * 4 + 2] = v.z;
            Bs[row][c8 * 4 + 3] = v.w;
        }
        __syncthreads();
#pragma unroll
        for (int k = 0; k < 16; ++k) {
            float2 a01 = *reinterpret_cast<const float2*>(&As[k][ty * 2]);
            float2 b01 = *reinterpret_cast<const float2*>(&Bs[k][tx * 2]);
            acc[0][0] = fmaf(a01.x, b01.x, acc[0][0]);
            acc[0][1] = fmaf(a01.x, b01.y, acc[0][1]);
            acc[1][0] = fmaf(a01.y, b01.x, acc[1][0]);
            acc[1][1] = fmaf(a01.y, b01.y, acc[1][1]);
        }
    }
#pragma unroll
    for (int i = 0; i < 2; ++i) {
        float2 v = make_float2(acc[i][0], acc[i][1]);
        *reinterpret_cast<float2*>(&g_Phi[(m0 + ty * 2 + i) * DDIM + n0 + tx * 2]) = v;
    }
}

// ---------------------------------------------------------------------------
// Kernel 2: p2[c] = ||Phi_c||^2 (fp32) + fp16 copy of Phi.
// ---------------------------------------------------------------------------
__global__ __launch_bounds__(256) void p2_kernel() {
    int w = (blockIdx.x * blockDim.x + threadIdx.x) >> 5;
    int lane = threadIdx.x & 31;
    if (w >= CDIM) return;
    const float4* r = reinterpret_cast<const float4*>(&g_Phi[w * DDIM]);
    float4 a = r[lane];
    float4 b = r[lane + 32];
    __half* dh = &g_PhiH[w * DDIM];
    {
        __half2 h0 = __floats2half2_rn(a.x, a.y);
        __half2 h1 = __floats2half2_rn(a.z, a.w);
        *reinterpret_cast<__half2*>(&dh[lane * 4])     = h0;
        *reinterpret_cast<__half2*>(&dh[lane * 4 + 2]) = h1;
        __half2 h2 = __floats2half2_rn(b.x, b.y);
        __half2 h3 = __floats2half2_rn(b.z, b.w);
        *reinterpret_cast<__half2*>(&dh[128 + lane * 4])     = h2;
        *reinterpret_cast<__half2*>(&dh[128 + lane * 4 + 2]) = h3;
    }
    float s = a.x * a.x + a.y * a.y + a.z * a.z + a.w * a.w
            + b.x * b.x + b.y * b.y + b.z * b.z + b.w * b.w;
#pragma unroll
    for (int o = 16; o > 0; o >>= 1)
        s += __shfl_xor_sync(0xFFFFFFFFu, s, o);
    if (lane == 0) g_p2[w] = s;
}

// ---------------------------------------------------------------------------
// Kernel 3: single-pass fp16 mma.sync dots + argmin; Phi via TMA (SW128),
// 3-stage ring (2 stages of prefetch ahead). X stored as 4 SW128 chunks
// [128 rows][64 halves] (65536 B, self-consistent write/read swizzle).
// SMEM: X_OFF=0 (4x16K) | STG_OFF=65536 (3x16K stages; red arrays alias) |
//       MB_OFF=114688 (3 mbarriers).  2 CTAs/SM.
// ---------------------------------------------------------------------------
#define X_OFF     0
#define STG_OFF   65536
#define MB_OFF    114688
#define SMEM_TOTAL 114752

__global__ __launch_bounds__(256, 2)
void dist_kernel(const float* __restrict__ X, float* __restrict__ out,
                 const __grid_constant__ CUtensorMap tmapH) {
    extern __shared__ __align__(1024) char smem[];
    const unsigned SB = smem_u32(smem);
    const unsigned MB = SB + MB_OFF;
    // Reduction arrays alias the TMA stage buffers (used only after mainloop).
    float* red_v = reinterpret_cast<float*>(smem + STG_OFF);
    int*   red_i = reinterpret_cast<int*>(smem + STG_OFF + 8192);
    float* red_s = reinterpret_cast<float*>(smem + STG_OFF + 16384);

    const int tid = threadIdx.x;
    const int lane = tid & 31, wid = tid >> 5;
    const int wm = wid >> 2, wn = wid & 3;
    const int mBase = wm * 64, nBase = wn * 32;
    const int rowBase = blockIdx.x * 128;

    if (tid == 0) {
        MBARRIER_INIT(MB + 0, 1);     // full[0]
        MBARRIER_INIT(MB + 8, 1);     // full[1]
        MBARRIER_INIT(MB + 16, 1);    // full[2]
    }

    // ---- X tile fill: fp32 -> fp16, 4 SW128 chunks of [128r][64 halves] ----
    for (int i = tid; i < 128 * 128; i += 256) {
        int r = i >> 7, kp = i & 127;          // kp indexes half2 pairs
        int k = kp * 2;
        int gr = rowBase + r;
        float2 v = make_float2(0.f, 0.f);
        if (gr < NPTS)
            v = *reinterpret_cast<const float2*>(&X[(size_t)gr * DDIM + k]);
        int chunk = k >> 6, kin = k & 63;
        unsigned sw = SWZ128((unsigned)(r * 128 + kin * 2));
        *reinterpret_cast<__half2*>(smem + X_OFF + chunk * 16384 + sw) =
            __floats2half2_rn(v.x, v.y);
    }
    __syncthreads();

    // Prologue: fill stages 0,1,2 with g=0,1,2
    if (tid == 0) {
#pragma unroll
        for (int g = 0; g < 3; ++g) {
            MBARRIER_EXPECT_TX(MB + (unsigned)g * 8, 16384);
            tma2d(SB + STG_OFF + (unsigned)g * 16384, &tmapH,
                  (g & 3) * 64, (g >> 2) * 128, MB + (unsigned)g * 8);
        }
    }

    // ldmatrix lane addressing
    const int arow = lane & 15;
    const int ahalf = lane >> 4;
    const int brow = (lane & 7) | ((lane >> 1) & 8);
    const int bhalf = (lane >> 3) & 1;

    int rowb[4];
#pragma unroll
    for (int mt = 0; mt < 4; ++mt)
        rowb[mt] = (mBase + mt * 16 + arow) * 128;

    float bestv[8], secondv[8];
    int   besti[8];
#pragma unroll
    for (int i = 0; i < 8; ++i) {
        bestv[i] = 3.402823466e38f; secondv[i] = 3.402823466e38f; besti[i] = 0;
    }

    float acc[4][4][4];
#pragma unroll
    for (int mt = 0; mt < 4; ++mt)
#pragma unroll
        for (int nt = 0; nt < 4; ++nt)
#pragma unroll
            for (int e = 0; e < 4; ++e) acc[mt][nt][e] = 0.f;

    for (int g = 0; g < 32; ++g) {                   // g = ct*4 + kc
        const int s = g % 3;                          // stage
        const int f = g / 3;                          // fill index -> parity
        const int kc = g & 3;
        mbar_wait(MB + (unsigned)s * 8, (unsigned)(f & 1));
        const unsigned stH = SB + STG_OFF + (unsigned)s * 16384;
        const unsigned xCh = SB + X_OFF + (unsigned)kc * 16384;
#pragma unroll
        for (int ks = 0; ks < 4; ++ks) {
            unsigned ah[4][4];
#pragma unroll
            for (int mt = 0; mt < 4; ++mt) {
                unsigned o = SWZ128((unsigned)(rowb[mt] + ks * 32 + ahalf * 16));
                LDSM4(ah[mt][0], ah[mt][1], ah[mt][2], ah[mt][3], xCh + o);
            }
            unsigned bh[4][2];
#pragma unroll
            for (int nt2 = 0; nt2 < 2; ++nt2) {
                unsigned off = (unsigned)((nBase + nt2 * 16 + brow) * 128 +
                                          ks * 32 + bhalf * 16);
                off = SWZ128(off);
                LDSM4(bh[nt2 * 2][0], bh[nt2 * 2][1],
                      bh[nt2 * 2 + 1][0], bh[nt2 * 2 + 1][1], stH + off);
            }
#pragma unroll
            for (int mt = 0; mt < 4; ++mt)
#pragma unroll
                for (int nt = 0; nt < 4; ++nt)
                    MMA16816F16(acc[mt][nt], ah[mt], bh[nt]);
        }
        __syncthreads();                             // stage s fully consumed
        if (tid == 0 && g + 3 < 32) {
            int g2 = g + 3;                          // refill same stage s
            MBARRIER_EXPECT_TX(MB + (unsigned)s * 8, 16384);
            tma2d(SB + STG_OFF + (unsigned)s * 16384, &tmapH,
                  (g2 & 3) * 64, (g2 >> 2) * 128, MB + (unsigned)s * 8);
        }
        if (kc == 3) {                               // full K done: fold argmin
            const int colBase = (g >> 2) * 128;
#pragma unroll
            for (int nt = 0; nt < 4; ++nt) {
                int c0 = colBase + nBase + nt * 8 + (lane & 3) * 2;
                float p2a = __ldg(&g_p2[c0]);
                float p2b = __ldg(&g_p2[c0 + 1]);
#pragma unroll
                for (int mt = 0; mt < 4; ++mt) {
                    float sc[4];
                    sc[0] = fmaf(-2.f, acc[mt][nt][0], p2a);
                    sc[1] = fmaf(-2.f, acc[mt][nt][1], p2b);
                    sc[2] = fmaf(-2.f, acc[mt][nt][2], p2a);
                    sc[3] = fmaf(-2.f, acc[mt][nt][3], p2b);
#pragma unroll
                    for (int e = 0; e < 4; ++e) {
                        int slot = mt * 2 + (e >> 1);
                        int c = c0 + (e & 1);
                        if (sc[e] < bestv[slot]) {
                            secondv[slot] = bestv[slot];
                            bestv[slot] = sc[e]; besti[slot] = c;
                        } else if (sc[e] < secondv[slot]) {
                            secondv[slot] = sc[e];
                        }
                        acc[mt][nt][e] = 0.f;
                    }
                }
            }
        }
    }

    // ---- Cross-thread reduction: 16 (best, idx, second) triples per row ----
    __syncthreads();   // stage buffers now reused as red arrays
#pragma unroll
    for (int mt = 0; mt < 4; ++mt)
#pragma unroll
        for (int h = 0; h < 2; ++h) {
            int r = mBase + mt * 16 + (lane >> 2) + h * 8;
            red_v[r * 16 + wn * 4 + (lane & 3)] = bestv[mt * 2 + h];
            red_i[r * 16 + wn * 4 + (lane & 3)] = besti[mt * 2 + h];
            red_s[r * 16 + wn * 4 + (lane & 3)] = secondv[mt * 2 + h];
        }
    __syncthreads();

    if (tid < 128) {
        int gr = rowBase + tid;
        if (gr < NPTS) {
            float bv = red_v[tid * 16];
            int   bi = red_i[tid * 16];
            float sv = red_s[tid * 16];
#pragma unroll
            for (int t = 1; t < 16; ++t) {
                float v  = red_v[tid * 16 + t];
                int   ii = red_i[tid * 16 + t];
                float s2 = red_s[tid * 16 + t];
                if (v < bv || (v == bv && ii < bi)) {
                    sv = fminf(s2, bv);
                    bv = v; bi = ii;
                } else {
                    sv = fminf(sv, v);
                }
            }
            if (sv - bv < THRESH) {            // near-tie -> exact refinement
                int w = atomicAdd(&g_cnt, 1);
                g_list[w] = gr;
                g_best[w] = 0xFFFFFFFFFFFFFFFFull;
            }
            const float4* xr = reinterpret_cast<const float4*>(&X[(size_t)gr * DDIM]);
            float x2 = 0.f;
#pragma unroll 8
            for (int t = 0; t < 64; ++t) {
                float4 v = xr[t];
                x2 += v.x * v.x + v.y * v.y + v.z * v.z + v.w * v.w;
            }
            float d2 = fmaxf(x2 + bv, 0.f);
            out[gr]        = (float)bi;
            out[NPTS + gr] = sqrtf(d2);
        }
    }
}

// ---------------------------------------------------------------------------
// Kernel 4a: exact fp32 refinement, parallel over (point x 128-centroid tile).
// Coalesced Phi reads: lane holds x[4l..4l+3] and x[128+4l..+3]; per centroid
// two CONTIGUOUS float4 loads (pr[lane], pr[32+lane]).
// ---------------------------------------------------------------------------
__global__ __launch_bounds__(256) void refine_score(const float* __restrict__ X) {
    __shared__ __align__(16) float xsh[DDIM];
    __shared__ unsigned long long wmin[8];
    const int tid = threadIdx.x;
    const int lane = tid & 31, wid = tid >> 5;
    const int ntask = g_cnt * 8;

    for (int task = blockIdx.x; task < ntask; task += gridDim.x) {
        const int w = task >> 3;
        const int ctb = (task & 7) * 128;
        const int gr = g_list[w];
        __syncthreads();                       // protect xsh/wmin reuse
        if (tid < 64)
            reinterpret_cast<float4*>(xsh)[tid] =
                reinterpret_cast<const float4*>(&X[(size_t)gr * DDIM])[tid];
        __syncthreads();

        float xf[8];
#pragma unroll
        for (int i = 0; i < 4; ++i) xf[i] = xsh[lane * 4 + i];
#pragma unroll
        for (int i = 0; i < 4; ++i) xf[4 + i] = xsh[128 + lane * 4 + i];

        float bv = 3.402823466e38f; int bi = 0;
        const int cw = ctb + wid * 16;
        for (int c0 = cw; c0 < cw + 16; c0 += 4) {
            float d[4];
#pragma unroll
            for (int q = 0; q < 4; ++q) {
                const float4* pr = reinterpret_cast<const float4*>(
                    &g_Phi[(size_t)(c0 + q) * DDIM]);
                float4 p0 = pr[lane];            // k = lane*4 .. +3
                float4 p1 = pr[32 + lane];       // k = 128 + lane*4 .. +3
                float s;
                s = xf[0] * p0.x;
                s = fmaf(xf[1], p0.y, s);
                s = fmaf(xf[2], p0.z, s);
                s = fmaf(xf[3], p0.w, s);
                s = fmaf(xf[4], p1.x, s);
                s = fmaf(xf[5], p1.y, s);
                s = fmaf(xf[6], p1.z, s);
                s = fmaf(xf[7], p1.w, s);
                d[q] = s;
            }
#pragma unroll
            for (int q = 0; q < 4; ++q) {
#pragma unroll
                for (int o = 16; o > 0; o >>= 1)
                    d[q] += __shfl_xor_sync(0xFFFFFFFFu, d[q], o);
                float s = fmaf(-2.f, d[q], g_p2[c0 + q]);
                if (s < bv) { bv = s; bi = c0 + q; }   // ascending c: first-min
            }
        }
        if (lane == 0)
            wmin[wid] = ((unsigned long long)f2ord(bv) << 32) | (unsigned)bi;
        __syncthreads();
        if (tid == 0) {
            unsigned long long m = wmin[0];
#pragma unroll
            for (int t = 1; t < 8; ++t) m = (wmin[t] < m) ? wmin[t] : m;
            atomicMin(&g_best[w], m);
        }
    }
}

// ---------------------------------------------------------------------------
// Kernel 4b: writeback — decode per-point key, compute x2, store outputs.
// ---------------------------------------------------------------------------
__global__ __launch_bounds__(256) void refine_write(const float* __restrict__ X,
                                                    float* __restrict__ out) {
    const int lane = threadIdx.x & 31;
    const int gw = (blockIdx.x * 256 + threadIdx.x) >> 5;
    const int nw = gridDim.x * 8;
    const int nwork = g_cnt;

    for (int w = gw; w < nwork; w += nw) {
        const int gr = g_list[w];
        unsigned long long key = g_best[w];
        int bi = (int)(unsigned)(key & 0xFFFFFFFFull);
        float bv = ord2f((unsigned)(key >> 32));
        const float4* xr = reinterpret_cast<const float4*>(&X[(size_t)gr * DDIM]);
        float4 a = xr[lane];
        float4 b = xr[lane + 32];
        float x2 = a.x * a.x + a.y * a.y + a.z * a.z + a.w * a.w
                 + b.x * b.x + b.y * b.y + b.z * b.z + b.w * b.w;
#pragma unroll
        for (int o = 16; o > 0; o >>= 1)
            x2 += __shfl_xor_sync(0xFFFFFFFFu, x2, o);
        if (lane == 0) {
            out[gr]        = (float)bi;
            out[NPTS + gr] = sqrtf(fmaxf(x2 + bv, 0.f));
        }
    }
}

// ---------------------------------------------------------------------------
// Host launcher
// ---------------------------------------------------------------------------
typedef CUresult (*PFN_tmapEncode)(
    CUtensorMap*, CUtensorMapDataType, cuuint32_t, void*,
    const cuuint64_t*, const cuuint64_t*, const cuuint32_t*, const cuuint32_t*,
    CUtensorMapInterleave, CUtensorMapSwizzle, CUtensorMapL2promotion,
    CUtensorMapFloatOOBfill);

static PFN_tmapEncode get_encode_fn() {
    static PFN_tmapEncode fn = nullptr;
    if (!fn) {
        void* p = nullptr;
        cudaDriverEntryPointQueryResult st;
        cudaGetDriverEntryPointByVersion("cuTensorMapEncodeTiled", &p, 12000,
                                         cudaEnableDefault, &st);
        fn = (PFN_tmapEncode)p;
    }
    return fn;
}

static void make_phi_map(CUtensorMap* map, void* ptr) {
    cuuint64_t dims[2]    = {DDIM, CDIM};
    cuuint64_t strides[1] = {DDIM * 2};
    cuuint32_t box[2]     = {64, 128};
    cuuint32_t es[2]      = {1, 1};
    get_encode_fn()(map, CU_TENSOR_MAP_DATA_TYPE_FLOAT16, 2, ptr,
                    dims, strides, box, es,
                    CU_TENSOR_MAP_INTERLEAVE_NONE, CU_TENSOR_MAP_SWIZZLE_128B,
                    CU_TENSOR_MAP_L2_PROMOTION_L2_128B,
                    CU_TENSOR_MAP_FLOAT_OOB_FILL_NONE);
}

extern "C" void kernel_launch(void* const* d_in, const int* in_sizes, int n_in,
                              void* d_out, int out_size) {
    const float* X = (const float*)d_in[0];
    const float* parents = (const float*)d_in[1];
    const float* epsilon = (const float*)d_in[2];
    float* out = (float*)d_out;

    void* cntPtr = nullptr;
    cudaGetSymbolAddress(&cntPtr, g_cnt);
    cudaMemsetAsync(cntPtr, 0, sizeof(int));

    void* phiH = nullptr;
    cudaGetSymbolAddress(&phiH, g_PhiH);
    CUtensorMap tmapH;
    make_phi_map(&tmapH, phiH);

    phi_kernel<<<dim3(DDIM / 32, CDIM / 32), 256>>>(parents, epsilon);
    p2_kernel<<<(CDIM * 32) / 256, 256>>>();

    static bool attrSet = false;   // idempotent attribute set (not a guard on work)
    if (!attrSet) {
        cudaFuncSetAttribute(dist_kernel, cudaFuncAttributeMaxDynamicSharedMemorySize,
                             SMEM_TOTAL);
        attrSet = true;
    }
    dist_kernel<<<(NPTS + 127) / 128, 256, SMEM_TOTAL>>>(X, out, tmapH);
    refine_score<<<1184, 256>>>(X);
    refine_write<<<64, 256>>>(X, out);
}